// round 1
// baseline (speedup 1.0000x reference)
#include <cuda_runtime.h>
#include <math.h>
#include <stdint.h>

// Problem constants
#define BB   4
#define SS   2048
#define DIM  2048
#define NH   16
#define HD   128
#define TOK  (BB * SS)          // 8192
#define EPSF 1e-6f

// Scratch (device globals: allocation-free)
__device__ float g_q[(size_t)TOK * DIM];
__device__ float g_k[(size_t)TOK * DIM];
__device__ float g_v[(size_t)TOK * DIM];
__device__ float g_o[(size_t)TOK * DIM];

// ---------------------------------------------------------------------------
// SGEMM (NT): C[m][n] = sum_k A[m][k] * B[n][k]
// A: MxK row-major, B: NxK row-major, C: MxN row-major
// Tile 128x128x16, 256 threads, 8x8 per thread.
// b-fragment columns are strided (tc + 16*j) for conflict-free Bs reads.
// ---------------------------------------------------------------------------
#define GBM 128
#define GBN 128
#define GBK 16
#define ASTR 129  // padded smem stride

__global__ __launch_bounds__(256) void sgemm_nt(const float* __restrict__ A,
                                                const float* __restrict__ B,
                                                float* __restrict__ C,
                                                int M, int N, int K)
{
    __shared__ float As[GBK * ASTR];
    __shared__ float Bs[GBK * ASTR];

    const int bm = blockIdx.y * GBM;
    const int bn = blockIdx.x * GBN;
    const int tid = threadIdx.x;
    const int tr = tid >> 4;       // 0..15
    const int tc = tid & 15;       // 0..15

    // loader mapping: thread loads rows (lr, lr+64), k-cols [lc, lc+4)
    const int lr = tid >> 2;           // 0..63
    const int lc = (tid & 3) * 4;      // 0,4,8,12

    const float* Ap0 = A + (size_t)(bm + lr) * K + lc;
    const float* Ap1 = A + (size_t)(bm + lr + 64) * K + lc;
    const float* Bp0 = B + (size_t)(bn + lr) * K + lc;
    const float* Bp1 = B + (size_t)(bn + lr + 64) * K + lc;

    float acc[8][8];
#pragma unroll
    for (int i = 0; i < 8; i++)
#pragma unroll
        for (int j = 0; j < 8; j++) acc[i][j] = 0.f;

    for (int kt = 0; kt < K; kt += GBK) {
        float4 a0 = *(const float4*)(Ap0 + kt);
        float4 a1 = *(const float4*)(Ap1 + kt);
        float4 b0 = *(const float4*)(Bp0 + kt);
        float4 b1 = *(const float4*)(Bp1 + kt);

        As[(lc + 0) * ASTR + lr] = a0.x;
        As[(lc + 1) * ASTR + lr] = a0.y;
        As[(lc + 2) * ASTR + lr] = a0.z;
        As[(lc + 3) * ASTR + lr] = a0.w;
        As[(lc + 0) * ASTR + lr + 64] = a1.x;
        As[(lc + 1) * ASTR + lr + 64] = a1.y;
        As[(lc + 2) * ASTR + lr + 64] = a1.z;
        As[(lc + 3) * ASTR + lr + 64] = a1.w;

        Bs[(lc + 0) * ASTR + lr] = b0.x;
        Bs[(lc + 1) * ASTR + lr] = b0.y;
        Bs[(lc + 2) * ASTR + lr] = b0.z;
        Bs[(lc + 3) * ASTR + lr] = b0.w;
        Bs[(lc + 0) * ASTR + lr + 64] = b1.x;
        Bs[(lc + 1) * ASTR + lr + 64] = b1.y;
        Bs[(lc + 2) * ASTR + lr + 64] = b1.z;
        Bs[(lc + 3) * ASTR + lr + 64] = b1.w;

        __syncthreads();

#pragma unroll
        for (int k = 0; k < GBK; k++) {
            float a[8], b[8];
#pragma unroll
            for (int i = 0; i < 8; i++) a[i] = As[k * ASTR + tr * 8 + i];
#pragma unroll
            for (int j = 0; j < 8; j++) b[j] = Bs[k * ASTR + tc + 16 * j];
#pragma unroll
            for (int i = 0; i < 8; i++)
#pragma unroll
                for (int j = 0; j < 8; j++) acc[i][j] = fmaf(a[i], b[j], acc[i][j]);
        }
        __syncthreads();
    }

#pragma unroll
    for (int i = 0; i < 8; i++) {
        float* crow = C + (size_t)(bm + tr * 8 + i) * N + bn;
#pragma unroll
        for (int j = 0; j < 8; j++) crow[tc + 16 * j] = acc[i][j];
    }
}

// ---------------------------------------------------------------------------
// Fused per-head RMSNorm + RoPE (rotate-half). In place on q/k buffers.
// One block = one (token, head), 128 threads.
// ---------------------------------------------------------------------------
__global__ __launch_bounds__(128) void rmsnorm_rope_kernel(float* __restrict__ qk,
                                                           const float* __restrict__ w,
                                                           const float* __restrict__ cos_t,
                                                           const float* __restrict__ sin_t)
{
    const int token = blockIdx.y;
    const int h = blockIdx.x;
    const int d = threadIdx.x;        // 0..127
    const int s = token & (SS - 1);   // token % S

    float* ptr = qk + (size_t)token * DIM + h * HD;
    float v = ptr[d];

    // sum of squares over 128 lanes
    float sq = v * v;
#pragma unroll
    for (int off = 16; off > 0; off >>= 1)
        sq += __shfl_xor_sync(0xffffffffu, sq, off);

    __shared__ float wsum[4];
    const int wid = d >> 5;
    if ((d & 31) == 0) wsum[wid] = sq;
    __syncthreads();
    float tot = wsum[0] + wsum[1] + wsum[2] + wsum[3];

    float rms = rsqrtf(tot * (1.0f / HD) + EPSF);
    float xn = v * rms * w[d];

    __shared__ float xs[HD];
    xs[d] = xn;
    __syncthreads();

    float rot = (d < 64) ? -xs[d + 64] : xs[d - 64];
    float cv = cos_t[s * HD + d];
    float sv = sin_t[s * HD + d];
    ptr[d] = xn * cv + rot * sv;
}

// ---------------------------------------------------------------------------
// Causal flash attention, fp32. BQ=BK=64, HD=128, 256 threads (16x16).
// q pre-scaled by 1/sqrt(HD) at load. Online softmax state in registers.
// ---------------------------------------------------------------------------
#define FBQ 64
#define FBK 64
#define QSTR 129
#define KSTR 129
#define VSTR 128
#define PSTR 65

// smem floats: Qs 64*129 + Ks 64*129 + Vs 64*128 + Ps 64*65
#define FLASH_SMEM_FLOATS (64 * QSTR + 64 * KSTR + 64 * VSTR + 64 * PSTR)

__global__ __launch_bounds__(256) void flash_kernel(const float* __restrict__ q,
                                                    const float* __restrict__ k,
                                                    const float* __restrict__ v,
                                                    float* __restrict__ o)
{
    extern __shared__ float sm[];
    float* Qs = sm;
    float* Ks = Qs + 64 * QSTR;
    float* Vs = Ks + 64 * KSTR;
    float* Ps = Vs + 64 * VSTR;

    const int q0 = blockIdx.x * FBQ;
    const int bh = blockIdx.y;
    const int b = bh >> 4;
    const int h = bh & 15;
    const size_t base = (size_t)b * SS * DIM + (size_t)h * HD;

    const int tid = threadIdx.x;
    const int tr = tid >> 4;
    const int tc = tid & 15;
    const float scale = 0.08838834764831845f;  // 1/sqrt(128)

    // Load Q tile (scaled). 64 rows x 128 cols = 2048 float4s, 8 per thread.
#pragma unroll
    for (int p = 0; p < 8; p++) {
        int idx = tid + p * 256;
        int r = idx >> 5;
        int c4 = (idx & 31) * 4;
        float4 qv = *(const float4*)(q + base + (size_t)(q0 + r) * DIM + c4);
        Qs[r * QSTR + c4 + 0] = qv.x * scale;
        Qs[r * QSTR + c4 + 1] = qv.y * scale;
        Qs[r * QSTR + c4 + 2] = qv.z * scale;
        Qs[r * QSTR + c4 + 3] = qv.w * scale;
    }

    float m_i[4], l_i[4], accum[4][8];
#pragma unroll
    for (int i = 0; i < 4; i++) {
        m_i[i] = -INFINITY;
        l_i[i] = 0.f;
#pragma unroll
        for (int j = 0; j < 8; j++) accum[i][j] = 0.f;
    }

    const int nkb = q0 / FBK + 1;
    for (int kb = 0; kb < nkb; kb++) {
        const int k0 = kb * FBK;
        __syncthreads();  // prev-iter reads done (and Q tile visible on iter 0)

        // Load K, V tiles
#pragma unroll
        for (int p = 0; p < 8; p++) {
            int idx = tid + p * 256;
            int r = idx >> 5;
            int c4 = (idx & 31) * 4;
            float4 kv = *(const float4*)(k + base + (size_t)(k0 + r) * DIM + c4);
            Ks[r * KSTR + c4 + 0] = kv.x;
            Ks[r * KSTR + c4 + 1] = kv.y;
            Ks[r * KSTR + c4 + 2] = kv.z;
            Ks[r * KSTR + c4 + 3] = kv.w;
            float4 vv = *(const float4*)(v + base + (size_t)(k0 + r) * DIM + c4);
            *(float4*)(Vs + r * VSTR + c4) = vv;
        }
        __syncthreads();

        // S = Q K^T  (rows tr*4+i, cols tc*4+j)
        float s[4][4];
#pragma unroll
        for (int i = 0; i < 4; i++)
#pragma unroll
            for (int j = 0; j < 4; j++) s[i][j] = 0.f;

#pragma unroll 4
        for (int d = 0; d < HD; d++) {
            float qa[4], ka[4];
#pragma unroll
            for (int i = 0; i < 4; i++) qa[i] = Qs[(tr * 4 + i) * QSTR + d];
#pragma unroll
            for (int j = 0; j < 4; j++) ka[j] = Ks[(tc * 4 + j) * KSTR + d];
#pragma unroll
            for (int i = 0; i < 4; i++)
#pragma unroll
                for (int j = 0; j < 4; j++) s[i][j] = fmaf(qa[i], ka[j], s[i][j]);
        }

        // causal mask (only diagonal block needs it)
        if (k0 == q0) {
#pragma unroll
            for (int i = 0; i < 4; i++)
#pragma unroll
                for (int j = 0; j < 4; j++)
                    if (k0 + tc * 4 + j > q0 + tr * 4 + i) s[i][j] = -INFINITY;
        }

        // Online softmax (row stats live in registers; rows span 16 tc-lanes)
        float alpha[4];
#pragma unroll
        for (int i = 0; i < 4; i++) {
            float mx = fmaxf(fmaxf(s[i][0], s[i][1]), fmaxf(s[i][2], s[i][3]));
#pragma unroll
            for (int off = 8; off > 0; off >>= 1)
                mx = fmaxf(mx, __shfl_xor_sync(0xffffffffu, mx, off));
            float mnew = fmaxf(m_i[i], mx);
            float rs = 0.f;
#pragma unroll
            for (int j = 0; j < 4; j++) {
                float pe = __expf(s[i][j] - mnew);
                s[i][j] = pe;
                rs += pe;
            }
#pragma unroll
            for (int off = 8; off > 0; off >>= 1)
                rs += __shfl_xor_sync(0xffffffffu, rs, off);
            alpha[i] = __expf(m_i[i] - mnew);
            l_i[i] = l_i[i] * alpha[i] + rs;
            m_i[i] = mnew;
        }

        // Stage P
#pragma unroll
        for (int i = 0; i < 4; i++)
#pragma unroll
            for (int j = 0; j < 4; j++)
                Ps[(tr * 4 + i) * PSTR + tc * 4 + j] = s[i][j];
        __syncthreads();

        // O = O*alpha + P V   (cols tc + 16*j, conflict-free Vs reads)
#pragma unroll
        for (int i = 0; i < 4; i++)
#pragma unroll
            for (int j = 0; j < 8; j++) accum[i][j] *= alpha[i];

#pragma unroll 4
        for (int kc = 0; kc < FBK; kc++) {
            float pv[4], vv[8];
#pragma unroll
            for (int i = 0; i < 4; i++) pv[i] = Ps[(tr * 4 + i) * PSTR + kc];
#pragma unroll
            for (int j = 0; j < 8; j++) vv[j] = Vs[kc * VSTR + tc + 16 * j];
#pragma unroll
            for (int i = 0; i < 4; i++)
#pragma unroll
                for (int j = 0; j < 8; j++) accum[i][j] = fmaf(pv[i], vv[j], accum[i][j]);
        }
    }

    // Write out (normalized)
#pragma unroll
    for (int i = 0; i < 4; i++) {
        float inv = 1.0f / l_i[i];
        float* orow = o + base + (size_t)(q0 + tr * 4 + i) * DIM;
#pragma unroll
        for (int j = 0; j < 8; j++) orow[tc + 16 * j] = accum[i][j] * inv;
    }
}

// ---------------------------------------------------------------------------
// Launch
// Inputs: 0=x 1=rope_cos 2=rope_sin 3=attn_mask 4=wq 5=wk 6=wv 7=wo
//         8=q_norm_w 9=k_norm_w
// ---------------------------------------------------------------------------
extern "C" void kernel_launch(void* const* d_in, const int* in_sizes, int n_in,
                              void* d_out, int out_size)
{
    const float* x       = (const float*)d_in[0];
    const float* rope_c  = (const float*)d_in[1];
    const float* rope_s  = (const float*)d_in[2];
    const float* wq      = (const float*)d_in[4];
    const float* wk      = (const float*)d_in[5];
    const float* wv      = (const float*)d_in[6];
    const float* wo      = (const float*)d_in[7];
    const float* qnw     = (const float*)d_in[8];
    const float* knw     = (const float*)d_in[9];
    float* out = (float*)d_out;

    float *q, *k, *v, *o;
    cudaGetSymbolAddress((void**)&q, g_q);
    cudaGetSymbolAddress((void**)&k, g_k);
    cudaGetSymbolAddress((void**)&v, g_v);
    cudaGetSymbolAddress((void**)&o, g_o);

    dim3 ggrid(DIM / GBN, TOK / GBM);  // (16, 64)
    sgemm_nt<<<ggrid, 256>>>(x, wq, q, TOK, DIM, DIM);
    sgemm_nt<<<ggrid, 256>>>(x, wk, k, TOK, DIM, DIM);
    sgemm_nt<<<ggrid, 256>>>(x, wv, v, TOK, DIM, DIM);

    dim3 ngrid(NH, TOK);
    rmsnorm_rope_kernel<<<ngrid, 128>>>(q, qnw, rope_c, rope_s);
    rmsnorm_rope_kernel<<<ngrid, 128>>>(k, knw, rope_c, rope_s);

    const int flash_smem = FLASH_SMEM_FLOATS * sizeof(float);
    cudaFuncSetAttribute(flash_kernel, cudaFuncAttributeMaxDynamicSharedMemorySize,
                         flash_smem);
    dim3 fgrid(SS / FBQ, BB * NH);  // (32, 64)
    flash_kernel<<<fgrid, 256, flash_smem>>>(q, k, v, o);

    sgemm_nt<<<ggrid, 256>>>(o, wo, out, TOK, DIM, DIM);
}

// round 2
// speedup vs baseline: 1.8740x; 1.8740x over previous
#include <cuda_runtime.h>
#include <math.h>
#include <stdint.h>

// Problem constants
#define BB   4
#define SS   2048
#define DIM  2048
#define NH   16
#define HD   128
#define TOK  (BB * SS)          // 8192
#define EPSF 1e-6f

// Scratch (device globals: allocation-free)
__device__ float g_q[(size_t)TOK * DIM];
__device__ float g_k[(size_t)TOK * DIM];
__device__ float g_v[(size_t)TOK * DIM];
__device__ float g_o[(size_t)TOK * DIM];

// ---------------------------------------------------------------------------
// TF32 tensor-core GEMM (NT): C[m][n] = sum_k A[m][k] * B[n][k]
// A: MxK row-major, B: NxK row-major, C: MxN row-major.
// CTA tile 128x128x16, 8 warps (2m x 4n), warp tile 64x32.
// mma.sync.aligned.m16n8k8.row.col.f32.tf32.tf32.f32
// Smem stride 20 floats -> (20g + c) mod 32 is a bank permutation:
// conflict-free fragment loads.
// ---------------------------------------------------------------------------
#define TBM 128
#define TBN 128
#define TBK 16
#define AST 20

__device__ __forceinline__ uint32_t f2tf(float f) {
    uint32_t o;
    asm("cvt.rna.tf32.f32 %0, %1;" : "=r"(o) : "f"(f));
    return o;
}

__device__ __forceinline__ void mma_tf32(float c[4], uint32_t a0, uint32_t a1,
                                         uint32_t a2, uint32_t a3,
                                         uint32_t b0, uint32_t b1) {
    asm volatile(
        "mma.sync.aligned.m16n8k8.row.col.f32.tf32.tf32.f32 "
        "{%0,%1,%2,%3}, {%4,%5,%6,%7}, {%8,%9}, {%0,%1,%2,%3};"
        : "+f"(c[0]), "+f"(c[1]), "+f"(c[2]), "+f"(c[3])
        : "r"(a0), "r"(a1), "r"(a2), "r"(a3), "r"(b0), "r"(b1));
}

__global__ __launch_bounds__(256) void gemm_tf32(const float* __restrict__ A,
                                                 const float* __restrict__ B,
                                                 float* __restrict__ C,
                                                 int M, int N, int K)
{
    __shared__ uint32_t As[2][TBM * AST];
    __shared__ uint32_t Bs[2][TBN * AST];

    const int bm = blockIdx.y * TBM;
    const int bn = blockIdx.x * TBN;
    const int tid = threadIdx.x;
    const int warp = tid >> 5;
    const int lane = tid & 31;
    const int g = lane >> 2;        // group id 0..7
    const int cth = lane & 3;       // thread-in-group 0..3
    const int wm = warp & 1;        // 0..1 -> 64 rows each
    const int wn = warp >> 1;       // 0..3 -> 32 cols each

    // gmem loader mapping: thread covers one row, 8 k-cols
    const int lr = tid >> 1;             // 0..127
    const int lc = (tid & 1) * 8;        // 0 or 8
    const float* Ag = A + (size_t)(bm + lr) * K + lc;
    const float* Bg = B + (size_t)(bn + lr) * K + lc;

    float acc[4][4][4];
#pragma unroll
    for (int mi = 0; mi < 4; mi++)
#pragma unroll
        for (int ni = 0; ni < 4; ni++)
#pragma unroll
            for (int e = 0; e < 4; e++) acc[mi][ni][e] = 0.f;

    const int ntiles = K / TBK;

    // load tile 0
    float4 ra0 = *(const float4*)(Ag);
    float4 ra1 = *(const float4*)(Ag + 4);
    float4 rb0 = *(const float4*)(Bg);
    float4 rb1 = *(const float4*)(Bg + 4);
    {
        uint32_t* as = &As[0][lr * AST + lc];
        as[0] = f2tf(ra0.x); as[1] = f2tf(ra0.y); as[2] = f2tf(ra0.z); as[3] = f2tf(ra0.w);
        as[4] = f2tf(ra1.x); as[5] = f2tf(ra1.y); as[6] = f2tf(ra1.z); as[7] = f2tf(ra1.w);
        uint32_t* bs = &Bs[0][lr * AST + lc];
        bs[0] = f2tf(rb0.x); bs[1] = f2tf(rb0.y); bs[2] = f2tf(rb0.z); bs[3] = f2tf(rb0.w);
        bs[4] = f2tf(rb1.x); bs[5] = f2tf(rb1.y); bs[6] = f2tf(rb1.z); bs[7] = f2tf(rb1.w);
    }
    __syncthreads();

    for (int t = 0; t < ntiles; t++) {
        // prefetch next tile into regs
        if (t + 1 < ntiles) {
            const int off = (t + 1) * TBK;
            ra0 = *(const float4*)(Ag + off);
            ra1 = *(const float4*)(Ag + off + 4);
            rb0 = *(const float4*)(Bg + off);
            rb1 = *(const float4*)(Bg + off + 4);
        }

        const uint32_t* as = As[t & 1];
        const uint32_t* bs = Bs[t & 1];

#pragma unroll
        for (int ks = 0; ks < TBK; ks += 8) {
            uint32_t a[4][4], b[4][2];
#pragma unroll
            for (int mi = 0; mi < 4; mi++) {
                const int rb = wm * 64 + mi * 16 + g;
                a[mi][0] = as[rb * AST + ks + cth];
                a[mi][1] = as[(rb + 8) * AST + ks + cth];
                a[mi][2] = as[rb * AST + ks + cth + 4];
                a[mi][3] = as[(rb + 8) * AST + ks + cth + 4];
            }
#pragma unroll
            for (int ni = 0; ni < 4; ni++) {
                const int cb = wn * 32 + ni * 8 + g;
                b[ni][0] = bs[cb * AST + ks + cth];
                b[ni][1] = bs[cb * AST + ks + cth + 4];
            }
#pragma unroll
            for (int mi = 0; mi < 4; mi++)
#pragma unroll
                for (int ni = 0; ni < 4; ni++)
                    mma_tf32(acc[mi][ni], a[mi][0], a[mi][1], a[mi][2], a[mi][3],
                             b[ni][0], b[ni][1]);
        }

        if (t + 1 < ntiles) {
            uint32_t* asn = &As[(t + 1) & 1][lr * AST + lc];
            asn[0] = f2tf(ra0.x); asn[1] = f2tf(ra0.y); asn[2] = f2tf(ra0.z); asn[3] = f2tf(ra0.w);
            asn[4] = f2tf(ra1.x); asn[5] = f2tf(ra1.y); asn[6] = f2tf(ra1.z); asn[7] = f2tf(ra1.w);
            uint32_t* bsn = &Bs[(t + 1) & 1][lr * AST + lc];
            bsn[0] = f2tf(rb0.x); bsn[1] = f2tf(rb0.y); bsn[2] = f2tf(rb0.z); bsn[3] = f2tf(rb0.w);
            bsn[4] = f2tf(rb1.x); bsn[5] = f2tf(rb1.y); bsn[6] = f2tf(rb1.z); bsn[7] = f2tf(rb1.w);
            __syncthreads();
        }
    }

    // Epilogue: c0,c1 -> (row, col..col+1); c2,c3 -> (row+8, ...)
#pragma unroll
    for (int mi = 0; mi < 4; mi++) {
        const int r0 = bm + wm * 64 + mi * 16 + g;
#pragma unroll
        for (int ni = 0; ni < 4; ni++) {
            const int col = bn + wn * 32 + ni * 8 + cth * 2;
            float2 v01 = make_float2(acc[mi][ni][0], acc[mi][ni][1]);
            float2 v23 = make_float2(acc[mi][ni][2], acc[mi][ni][3]);
            *(float2*)(C + (size_t)r0 * N + col) = v01;
            *(float2*)(C + (size_t)(r0 + 8) * N + col) = v23;
        }
    }
}

// ---------------------------------------------------------------------------
// Fused per-head RMSNorm + RoPE (rotate-half). In place on q/k buffers.
// ---------------------------------------------------------------------------
__global__ __launch_bounds__(128) void rmsnorm_rope_kernel(float* __restrict__ qk,
                                                           const float* __restrict__ w,
                                                           const float* __restrict__ cos_t,
                                                           const float* __restrict__ sin_t)
{
    const int token = blockIdx.y;
    const int h = blockIdx.x;
    const int d = threadIdx.x;        // 0..127
    const int s = token & (SS - 1);   // token % S

    float* ptr = qk + (size_t)token * DIM + h * HD;
    float v = ptr[d];

    float sq = v * v;
#pragma unroll
    for (int off = 16; off > 0; off >>= 1)
        sq += __shfl_xor_sync(0xffffffffu, sq, off);

    __shared__ float wsum[4];
    const int wid = d >> 5;
    if ((d & 31) == 0) wsum[wid] = sq;
    __syncthreads();
    float tot = wsum[0] + wsum[1] + wsum[2] + wsum[3];

    float rms = rsqrtf(tot * (1.0f / HD) + EPSF);
    float xn = v * rms * w[d];

    __shared__ float xs[HD];
    xs[d] = xn;
    __syncthreads();

    float rot = (d < 64) ? -xs[d + 64] : xs[d - 64];
    float cv = cos_t[s * HD + d];
    float sv = sin_t[s * HD + d];
    ptr[d] = xn * cv + rot * sv;
}

// ---------------------------------------------------------------------------
// Causal flash attention, fp32. BQ=BK=64, HD=128, 256 threads (16x16).
// ---------------------------------------------------------------------------
#define FBQ 64
#define FBK 64
#define QSTR 129
#define KSTR 129
#define VSTR 128
#define PSTR 65

#define FLASH_SMEM_FLOATS (64 * QSTR + 64 * KSTR + 64 * VSTR + 64 * PSTR)

__global__ __launch_bounds__(256) void flash_kernel(const float* __restrict__ q,
                                                    const float* __restrict__ k,
                                                    const float* __restrict__ v,
                                                    float* __restrict__ o)
{
    extern __shared__ float sm[];
    float* Qs = sm;
    float* Ks = Qs + 64 * QSTR;
    float* Vs = Ks + 64 * KSTR;
    float* Ps = Vs + 64 * VSTR;

    const int q0 = blockIdx.x * FBQ;
    const int bh = blockIdx.y;
    const int b = bh >> 4;
    const int h = bh & 15;
    const size_t base = (size_t)b * SS * DIM + (size_t)h * HD;

    const int tid = threadIdx.x;
    const int tr = tid >> 4;
    const int tc = tid & 15;
    const float scale = 0.08838834764831845f;  // 1/sqrt(128)

#pragma unroll
    for (int p = 0; p < 8; p++) {
        int idx = tid + p * 256;
        int r = idx >> 5;
        int c4 = (idx & 31) * 4;
        float4 qv = *(const float4*)(q + base + (size_t)(q0 + r) * DIM + c4);
        Qs[r * QSTR + c4 + 0] = qv.x * scale;
        Qs[r * QSTR + c4 + 1] = qv.y * scale;
        Qs[r * QSTR + c4 + 2] = qv.z * scale;
        Qs[r * QSTR + c4 + 3] = qv.w * scale;
    }

    float m_i[4], l_i[4], accum[4][8];
#pragma unroll
    for (int i = 0; i < 4; i++) {
        m_i[i] = -INFINITY;
        l_i[i] = 0.f;
#pragma unroll
        for (int j = 0; j < 8; j++) accum[i][j] = 0.f;
    }

    const int nkb = q0 / FBK + 1;
    for (int kb = 0; kb < nkb; kb++) {
        const int k0 = kb * FBK;
        __syncthreads();

#pragma unroll
        for (int p = 0; p < 8; p++) {
            int idx = tid + p * 256;
            int r = idx >> 5;
            int c4 = (idx & 31) * 4;
            float4 kv = *(const float4*)(k + base + (size_t)(k0 + r) * DIM + c4);
            Ks[r * KSTR + c4 + 0] = kv.x;
            Ks[r * KSTR + c4 + 1] = kv.y;
            Ks[r * KSTR + c4 + 2] = kv.z;
            Ks[r * KSTR + c4 + 3] = kv.w;
            float4 vv = *(const float4*)(v + base + (size_t)(k0 + r) * DIM + c4);
            *(float4*)(Vs + r * VSTR + c4) = vv;
        }
        __syncthreads();

        float s[4][4];
#pragma unroll
        for (int i = 0; i < 4; i++)
#pragma unroll
            for (int j = 0; j < 4; j++) s[i][j] = 0.f;

#pragma unroll 4
        for (int d = 0; d < HD; d++) {
            float qa[4], ka[4];
#pragma unroll
            for (int i = 0; i < 4; i++) qa[i] = Qs[(tr * 4 + i) * QSTR + d];
#pragma unroll
            for (int j = 0; j < 4; j++) ka[j] = Ks[(tc * 4 + j) * KSTR + d];
#pragma unroll
            for (int i = 0; i < 4; i++)
#pragma unroll
                for (int j = 0; j < 4; j++) s[i][j] = fmaf(qa[i], ka[j], s[i][j]);
        }

        if (k0 == q0) {
#pragma unroll
            for (int i = 0; i < 4; i++)
#pragma unroll
                for (int j = 0; j < 4; j++)
                    if (k0 + tc * 4 + j > q0 + tr * 4 + i) s[i][j] = -INFINITY;
        }

        float alpha[4];
#pragma unroll
        for (int i = 0; i < 4; i++) {
            float mx = fmaxf(fmaxf(s[i][0], s[i][1]), fmaxf(s[i][2], s[i][3]));
#pragma unroll
            for (int off = 8; off > 0; off >>= 1)
                mx = fmaxf(mx, __shfl_xor_sync(0xffffffffu, mx, off));
            float mnew = fmaxf(m_i[i], mx);
            float rs = 0.f;
#pragma unroll
            for (int j = 0; j < 4; j++) {
                float pe = __expf(s[i][j] - mnew);
                s[i][j] = pe;
                rs += pe;
            }
#pragma unroll
            for (int off = 8; off > 0; off >>= 1)
                rs += __shfl_xor_sync(0xffffffffu, rs, off);
            alpha[i] = __expf(m_i[i] - mnew);
            l_i[i] = l_i[i] * alpha[i] + rs;
            m_i[i] = mnew;
        }

#pragma unroll
        for (int i = 0; i < 4; i++)
#pragma unroll
            for (int j = 0; j < 4; j++)
                Ps[(tr * 4 + i) * PSTR + tc * 4 + j] = s[i][j];
        __syncthreads();

#pragma unroll
        for (int i = 0; i < 4; i++)
#pragma unroll
            for (int j = 0; j < 8; j++) accum[i][j] *= alpha[i];

#pragma unroll 4
        for (int kc = 0; kc < FBK; kc++) {
            float pv[4], vv[8];
#pragma unroll
            for (int i = 0; i < 4; i++) pv[i] = Ps[(tr * 4 + i) * PSTR + kc];
#pragma unroll
            for (int j = 0; j < 8; j++) vv[j] = Vs[kc * VSTR + tc + 16 * j];
#pragma unroll
            for (int i = 0; i < 4; i++)
#pragma unroll
                for (int j = 0; j < 8; j++) accum[i][j] = fmaf(pv[i], vv[j], accum[i][j]);
        }
    }

#pragma unroll
    for (int i = 0; i < 4; i++) {
        float inv = 1.0f / l_i[i];
        float* orow = o + base + (size_t)(q0 + tr * 4 + i) * DIM;
#pragma unroll
        for (int j = 0; j < 8; j++) orow[tc + 16 * j] = accum[i][j] * inv;
    }
}

// ---------------------------------------------------------------------------
// Launch
// Inputs: 0=x 1=rope_cos 2=rope_sin 3=attn_mask 4=wq 5=wk 6=wv 7=wo
//         8=q_norm_w 9=k_norm_w
// ---------------------------------------------------------------------------
extern "C" void kernel_launch(void* const* d_in, const int* in_sizes, int n_in,
                              void* d_out, int out_size)
{
    const float* x       = (const float*)d_in[0];
    const float* rope_c  = (const float*)d_in[1];
    const float* rope_s  = (const float*)d_in[2];
    const float* wq      = (const float*)d_in[4];
    const float* wk      = (const float*)d_in[5];
    const float* wv      = (const float*)d_in[6];
    const float* wo      = (const float*)d_in[7];
    const float* qnw     = (const float*)d_in[8];
    const float* knw     = (const float*)d_in[9];
    float* out = (float*)d_out;

    float *q, *k, *v, *o;
    cudaGetSymbolAddress((void**)&q, g_q);
    cudaGetSymbolAddress((void**)&k, g_k);
    cudaGetSymbolAddress((void**)&v, g_v);
    cudaGetSymbolAddress((void**)&o, g_o);

    dim3 ggrid(DIM / TBN, TOK / TBM);  // (16, 64)
    gemm_tf32<<<ggrid, 256>>>(x, wq, q, TOK, DIM, DIM);
    gemm_tf32<<<ggrid, 256>>>(x, wk, k, TOK, DIM, DIM);
    gemm_tf32<<<ggrid, 256>>>(x, wv, v, TOK, DIM, DIM);

    dim3 ngrid(NH, TOK);
    rmsnorm_rope_kernel<<<ngrid, 128>>>(q, qnw, rope_c, rope_s);
    rmsnorm_rope_kernel<<<ngrid, 128>>>(k, knw, rope_c, rope_s);

    const int flash_smem = FLASH_SMEM_FLOATS * sizeof(float);
    cudaFuncSetAttribute(flash_kernel, cudaFuncAttributeMaxDynamicSharedMemorySize,
                         flash_smem);
    dim3 fgrid(SS / FBQ, BB * NH);  // (32, 64)
    flash_kernel<<<fgrid, 256, flash_smem>>>(q, k, v, o);

    gemm_tf32<<<ggrid, 256>>>(o, wo, out, TOK, DIM, DIM);
}

// round 5
// speedup vs baseline: 2.7611x; 1.4734x over previous
#include <cuda_runtime.h>
#include <math.h>
#include <stdint.h>

// Problem constants
#define BB   4
#define SS   2048
#define DIM  2048
#define NH   16
#define HD   128
#define TOK  (BB * SS)          // 8192
#define EPSF 1e-6f

// Scratch (device globals: allocation-free)
__device__ float g_q[(size_t)TOK * DIM];
__device__ float g_k[(size_t)TOK * DIM];
__device__ float g_v[(size_t)TOK * DIM];
__device__ float g_o[(size_t)TOK * DIM];

// ---------------------------------------------------------------------------
// Common helpers
// ---------------------------------------------------------------------------
__device__ __forceinline__ uint32_t f2tf(float f) {
    uint32_t o;
    asm("cvt.rna.tf32.f32 %0, %1;" : "=r"(o) : "f"(f));
    return o;
}

__device__ __forceinline__ void mma_tf32(float c[4], uint32_t a0, uint32_t a1,
                                         uint32_t a2, uint32_t a3,
                                         uint32_t b0, uint32_t b1) {
    asm volatile(
        "mma.sync.aligned.m16n8k8.row.col.f32.tf32.tf32.f32 "
        "{%0,%1,%2,%3}, {%4,%5,%6,%7}, {%8,%9}, {%0,%1,%2,%3};"
        : "+f"(c[0]), "+f"(c[1]), "+f"(c[2]), "+f"(c[3])
        : "r"(a0), "r"(a1), "r"(a2), "r"(a3), "r"(b0), "r"(b1));
}

// ---------------------------------------------------------------------------
// TF32 tensor-core GEMM (NT): C[m][n] = sum_k A[m][k] * B[n][k]   (unchanged R2)
// CTA tile 128x128x16, 8 warps (2m x 4n), warp tile 64x32.
// ---------------------------------------------------------------------------
#define TBM 128
#define TBN 128
#define TBK 16
#define AST 20

__global__ __launch_bounds__(256) void gemm_tf32(const float* __restrict__ A,
                                                 const float* __restrict__ B,
                                                 float* __restrict__ C,
                                                 int M, int N, int K)
{
    __shared__ uint32_t As[2][TBM * AST];
    __shared__ uint32_t Bs[2][TBN * AST];

    const int bm = blockIdx.y * TBM;
    const int bn = blockIdx.x * TBN;
    const int tid = threadIdx.x;
    const int warp = tid >> 5;
    const int lane = tid & 31;
    const int g = lane >> 2;
    const int cth = lane & 3;
    const int wm = warp & 1;
    const int wn = warp >> 1;

    const int lr = tid >> 1;
    const int lc = (tid & 1) * 8;
    const float* Ag = A + (size_t)(bm + lr) * K + lc;
    const float* Bg = B + (size_t)(bn + lr) * K + lc;

    float acc[4][4][4];
#pragma unroll
    for (int mi = 0; mi < 4; mi++)
#pragma unroll
        for (int ni = 0; ni < 4; ni++)
#pragma unroll
            for (int e = 0; e < 4; e++) acc[mi][ni][e] = 0.f;

    const int ntiles = K / TBK;

    float4 ra0 = *(const float4*)(Ag);
    float4 ra1 = *(const float4*)(Ag + 4);
    float4 rb0 = *(const float4*)(Bg);
    float4 rb1 = *(const float4*)(Bg + 4);
    {
        uint32_t* as = &As[0][lr * AST + lc];
        as[0] = f2tf(ra0.x); as[1] = f2tf(ra0.y); as[2] = f2tf(ra0.z); as[3] = f2tf(ra0.w);
        as[4] = f2tf(ra1.x); as[5] = f2tf(ra1.y); as[6] = f2tf(ra1.z); as[7] = f2tf(ra1.w);
        uint32_t* bs = &Bs[0][lr * AST + lc];
        bs[0] = f2tf(rb0.x); bs[1] = f2tf(rb0.y); bs[2] = f2tf(rb0.z); bs[3] = f2tf(rb0.w);
        bs[4] = f2tf(rb1.x); bs[5] = f2tf(rb1.y); bs[6] = f2tf(rb1.z); bs[7] = f2tf(rb1.w);
    }
    __syncthreads();

    for (int t = 0; t < ntiles; t++) {
        if (t + 1 < ntiles) {
            const int off = (t + 1) * TBK;
            ra0 = *(const float4*)(Ag + off);
            ra1 = *(const float4*)(Ag + off + 4);
            rb0 = *(const float4*)(Bg + off);
            rb1 = *(const float4*)(Bg + off + 4);
        }

        const uint32_t* as = As[t & 1];
        const uint32_t* bs = Bs[t & 1];

#pragma unroll
        for (int ks = 0; ks < TBK; ks += 8) {
            uint32_t a[4][4], b[4][2];
#pragma unroll
            for (int mi = 0; mi < 4; mi++) {
                const int rb = wm * 64 + mi * 16 + g;
                a[mi][0] = as[rb * AST + ks + cth];
                a[mi][1] = as[(rb + 8) * AST + ks + cth];
                a[mi][2] = as[rb * AST + ks + cth + 4];
                a[mi][3] = as[(rb + 8) * AST + ks + cth + 4];
            }
#pragma unroll
            for (int ni = 0; ni < 4; ni++) {
                const int cb = wn * 32 + ni * 8 + g;
                b[ni][0] = bs[cb * AST + ks + cth];
                b[ni][1] = bs[cb * AST + ks + cth + 4];
            }
#pragma unroll
            for (int mi = 0; mi < 4; mi++)
#pragma unroll
                for (int ni = 0; ni < 4; ni++)
                    mma_tf32(acc[mi][ni], a[mi][0], a[mi][1], a[mi][2], a[mi][3],
                             b[ni][0], b[ni][1]);
        }

        if (t + 1 < ntiles) {
            uint32_t* asn = &As[(t + 1) & 1][lr * AST + lc];
            asn[0] = f2tf(ra0.x); asn[1] = f2tf(ra0.y); asn[2] = f2tf(ra0.z); asn[3] = f2tf(ra0.w);
            asn[4] = f2tf(ra1.x); asn[5] = f2tf(ra1.y); asn[6] = f2tf(ra1.z); asn[7] = f2tf(ra1.w);
            uint32_t* bsn = &Bs[(t + 1) & 1][lr * AST + lc];
            bsn[0] = f2tf(rb0.x); bsn[1] = f2tf(rb0.y); bsn[2] = f2tf(rb0.z); bsn[3] = f2tf(rb0.w);
            bsn[4] = f2tf(rb1.x); bsn[5] = f2tf(rb1.y); bsn[6] = f2tf(rb1.z); bsn[7] = f2tf(rb1.w);
            __syncthreads();
        }
    }

#pragma unroll
    for (int mi = 0; mi < 4; mi++) {
        const int r0 = bm + wm * 64 + mi * 16 + g;
#pragma unroll
        for (int ni = 0; ni < 4; ni++) {
            const int col = bn + wn * 32 + ni * 8 + cth * 2;
            *(float2*)(C + (size_t)r0 * N + col) = make_float2(acc[mi][ni][0], acc[mi][ni][1]);
            *(float2*)(C + (size_t)(r0 + 8) * N + col) = make_float2(acc[mi][ni][2], acc[mi][ni][3]);
        }
    }
}

// ---------------------------------------------------------------------------
// Fused per-head RMSNorm + RoPE (rotate-half). In place on q/k buffers.
// ---------------------------------------------------------------------------
__global__ __launch_bounds__(128) void rmsnorm_rope_kernel(float* __restrict__ qk,
                                                           const float* __restrict__ w,
                                                           const float* __restrict__ cos_t,
                                                           const float* __restrict__ sin_t)
{
    const int token = blockIdx.y;
    const int h = blockIdx.x;
    const int d = threadIdx.x;
    const int s = token & (SS - 1);

    float* ptr = qk + (size_t)token * DIM + h * HD;
    float v = ptr[d];

    float sq = v * v;
#pragma unroll
    for (int off = 16; off > 0; off >>= 1)
        sq += __shfl_xor_sync(0xffffffffu, sq, off);

    __shared__ float wsum[4];
    const int wid = d >> 5;
    if ((d & 31) == 0) wsum[wid] = sq;
    __syncthreads();
    float tot = wsum[0] + wsum[1] + wsum[2] + wsum[3];

    float rms = rsqrtf(tot * (1.0f / HD) + EPSF);
    float xn = v * rms * w[d];

    __shared__ float xs[HD];
    xs[d] = xn;
    __syncthreads();

    float rot = (d < 64) ? -xs[d + 64] : xs[d - 64];
    ptr[d] = xn * cos_t[s * HD + d] + rot * sin_t[s * HD + d];
}

// ---------------------------------------------------------------------------
// Causal flash attention with tf32 mma.sync tensor cores.
// BQ=128, BK=64, HD=128. 256 threads = 8 warps; warp w owns q-rows w*16..+15.
// Strides chosen for conflict-free fragment LDS:
//   Q/K stride 132 (4g+cth distinct mod 32), V stride 136 (8cth+g distinct),
//   P stride 68.
// ---------------------------------------------------------------------------
#define FBQ 128
#define FBK 64
#define QSTR 132
#define KSTR 132
#define VSTR 136
#define PSTR 68

#define FLASH_SMEM_FLOATS (FBQ * QSTR + FBK * KSTR + FBK * VSTR + FBQ * PSTR)

__global__ __launch_bounds__(256) void flash_tc(const float* __restrict__ q,
                                                const float* __restrict__ k,
                                                const float* __restrict__ v,
                                                float* __restrict__ o)
{
    extern __shared__ float smf[];
    float* Qs = smf;                    // tf32 bits
    float* Ks = Qs + FBQ * QSTR;
    float* Vs = Ks + FBK * KSTR;
    float* Ps = Vs + FBK * VSTR;

    const int q0 = blockIdx.x * FBQ;
    const int bh = blockIdx.y;
    const int b = bh >> 4;
    const int h = bh & 15;
    const size_t base = (size_t)b * SS * DIM + (size_t)h * HD;

    const int tid = threadIdx.x;
    const int w = tid >> 5;
    const int lane = tid & 31;
    const int g = lane >> 2;          // 0..7
    const int cth = lane & 3;         // 0..3
    const float scale = 0.08838834764831845f;  // 1/sqrt(128)

    // ---- Load Q tile (scaled, tf32). 128x128 = 4096 float4, 16/thread ----
#pragma unroll
    for (int p = 0; p < 16; p++) {
        int idx = tid + p * 256;
        int r = idx >> 5;
        int c4 = (idx & 31) * 4;
        float4 qv = *(const float4*)(q + base + (size_t)(q0 + r) * DIM + c4);
        uint4 u;
        u.x = f2tf(qv.x * scale); u.y = f2tf(qv.y * scale);
        u.z = f2tf(qv.z * scale); u.w = f2tf(qv.w * scale);
        *(uint4*)(Qs + r * QSTR + c4) = u;
    }

    float m0 = -INFINITY, m1 = -INFINITY, l0 = 0.f, l1 = 0.f;
    float acc[16][4];
#pragma unroll
    for (int nb = 0; nb < 16; nb++)
#pragma unroll
        for (int e = 0; e < 4; e++) acc[nb][e] = 0.f;

    const int rowg = q0 + w * 16 + g;       // this thread's first row
    float* Qw = Qs + (w * 16) * QSTR;
    float* Pw = Ps + (w * 16) * PSTR;

    const int nkb = q0 / FBK + 2;
    for (int kb = 0; kb < nkb; kb++) {
        const int k0 = kb * FBK;
        __syncthreads();   // prior-iter Vs reads done; Q tile visible (iter 0)

        // ---- Load K, V tiles (tf32). 64x128 each = 2048 float4, 8/thread ----
#pragma unroll
        for (int p = 0; p < 8; p++) {
            int idx = tid + p * 256;
            int r = idx >> 5;
            int c4 = (idx & 31) * 4;
            float4 kv = *(const float4*)(k + base + (size_t)(k0 + r) * DIM + c4);
            uint4 uk;
            uk.x = f2tf(kv.x); uk.y = f2tf(kv.y); uk.z = f2tf(kv.z); uk.w = f2tf(kv.w);
            *(uint4*)(Ks + r * KSTR + c4) = uk;
            float4 vv = *(const float4*)(v + base + (size_t)(k0 + r) * DIM + c4);
            uint4 uv;
            uv.x = f2tf(vv.x); uv.y = f2tf(vv.y); uv.z = f2tf(vv.z); uv.w = f2tf(vv.w);
            *(uint4*)(Vs + r * VSTR + c4) = uv;
        }
        __syncthreads();

        // warp skips tiles strictly above its causal frontier
        if (k0 > q0 + w * 16 + 15) continue;

        // ---- S = Q K^T : 16 k-chunks x 8 n-blocks of m16n8k8 ----
        float c[8][4];
#pragma unroll
        for (int nb = 0; nb < 8; nb++)
#pragma unroll
            for (int e = 0; e < 4; e++) c[nb][e] = 0.f;

#pragma unroll 4
        for (int kc = 0; kc < 16; kc++) {
            const int kcol = kc * 8 + cth;
            uint32_t a0 = __float_as_uint(Qw[g * QSTR + kcol]);
            uint32_t a1 = __float_as_uint(Qw[(g + 8) * QSTR + kcol]);
            uint32_t a2 = __float_as_uint(Qw[g * QSTR + kcol + 4]);
            uint32_t a3 = __float_as_uint(Qw[(g + 8) * QSTR + kcol + 4]);
#pragma unroll
            for (int nb = 0; nb < 8; nb++) {
                uint32_t b0 = __float_as_uint(Ks[(nb * 8 + g) * KSTR + kcol]);
                uint32_t b1 = __float_as_uint(Ks[(nb * 8 + g) * KSTR + kcol + 4]);
                mma_tf32(c[nb], a0, a1, a2, a3, b0, b1);
            }
        }

        // ---- causal mask (only near-diagonal tiles) ----
        if (k0 + FBK - 1 > rowg) {
#pragma unroll
            for (int nb = 0; nb < 8; nb++) {
                const int col = k0 + nb * 8 + 2 * cth;
                if (col > rowg)         c[nb][0] = -INFINITY;
                if (col + 1 > rowg)     c[nb][1] = -INFINITY;
                if (col > rowg + 8)     c[nb][2] = -INFINITY;
                if (col + 1 > rowg + 8) c[nb][3] = -INFINITY;
            }
        }

        // ---- online softmax on C-fragment layout (2 quad shuffles/row) ----
        float mx0 = -INFINITY, mx1 = -INFINITY;
#pragma unroll
        for (int nb = 0; nb < 8; nb++) {
            mx0 = fmaxf(mx0, fmaxf(c[nb][0], c[nb][1]));
            mx1 = fmaxf(mx1, fmaxf(c[nb][2], c[nb][3]));
        }
        mx0 = fmaxf(mx0, __shfl_xor_sync(0xffffffffu, mx0, 1));
        mx0 = fmaxf(mx0, __shfl_xor_sync(0xffffffffu, mx0, 2));
        mx1 = fmaxf(mx1, __shfl_xor_sync(0xffffffffu, mx1, 1));
        mx1 = fmaxf(mx1, __shfl_xor_sync(0xffffffffu, mx1, 2));

        const float mn0 = fmaxf(m0, mx0);
        const float mn1 = fmaxf(m1, mx1);
        float rs0 = 0.f, rs1 = 0.f;
#pragma unroll
        for (int nb = 0; nb < 8; nb++) {
            c[nb][0] = __expf(c[nb][0] - mn0);
            c[nb][1] = __expf(c[nb][1] - mn0);
            c[nb][2] = __expf(c[nb][2] - mn1);
            c[nb][3] = __expf(c[nb][3] - mn1);
            rs0 += c[nb][0] + c[nb][1];
            rs1 += c[nb][2] + c[nb][3];
        }
        rs0 += __shfl_xor_sync(0xffffffffu, rs0, 1);
        rs0 += __shfl_xor_sync(0xffffffffu, rs0, 2);
        rs1 += __shfl_xor_sync(0xffffffffu, rs1, 1);
        rs1 += __shfl_xor_sync(0xffffffffu, rs1, 2);

        const float al0 = __expf(m0 - mn0);
        const float al1 = __expf(m1 - mn1);
        l0 = l0 * al0 + rs0;
        l1 = l1 * al1 + rs1;
        m0 = mn0;
        m1 = mn1;

#pragma unroll
        for (int nb = 0; nb < 16; nb++) {
            acc[nb][0] *= al0; acc[nb][1] *= al0;
            acc[nb][2] *= al1; acc[nb][3] *= al1;
        }

        // ---- stage P (tf32) in per-warp-private strip ----
#pragma unroll
        for (int nb = 0; nb < 8; nb++) {
            const int colb = nb * 8 + 2 * cth;
            *(uint2*)(Pw + g * PSTR + colb) = make_uint2(f2tf(c[nb][0]), f2tf(c[nb][1]));
            *(uint2*)(Pw + (g + 8) * PSTR + colb) = make_uint2(f2tf(c[nb][2]), f2tf(c[nb][3]));
        }
        __syncwarp();

        // ---- O += P V : 8 k-chunks x 16 n-blocks ----
#pragma unroll 2
        for (int kc = 0; kc < 8; kc++) {
            const int kr = kc * 8 + cth;
            uint32_t a0 = __float_as_uint(Pw[g * PSTR + kr]);
            uint32_t a1 = __float_as_uint(Pw[(g + 8) * PSTR + kr]);
            uint32_t a2 = __float_as_uint(Pw[g * PSTR + kr + 4]);
            uint32_t a3 = __float_as_uint(Pw[(g + 8) * PSTR + kr + 4]);
#pragma unroll
            for (int nb = 0; nb < 16; nb++) {
                uint32_t b0 = __float_as_uint(Vs[kr * VSTR + nb * 8 + g]);
                uint32_t b1 = __float_as_uint(Vs[(kr + 4) * VSTR + nb * 8 + g]);
                mma_tf32(acc[nb], a0, a1, a2, a3, b0, b1);
            }
        }
        __syncwarp();  // P reads done before next-iter overwrite
    }

    // ---- epilogue ----
    const float il0 = 1.0f / l0;
    const float il1 = 1.0f / l1;
    const size_t r0 = (size_t)rowg;
    const size_t r1 = (size_t)(rowg + 8);
#pragma unroll
    for (int nb = 0; nb < 16; nb++) {
        const int col = nb * 8 + 2 * cth;
        *(float2*)(o + base + r0 * DIM + col) = make_float2(acc[nb][0] * il0, acc[nb][1] * il0);
        *(float2*)(o + base + r1 * DIM + col) = make_float2(acc[nb][2] * il1, acc[nb][3] * il1);
    }
}

// ---------------------------------------------------------------------------
// Launch
// Inputs: 0=x 1=rope_cos 2=rope_sin 3=attn_mask 4=wq 5=wk 6=wv 7=wo
//         8=q_norm_w 9=k_norm_w
// ---------------------------------------------------------------------------
extern "C" void kernel_launch(void* const* d_in, const int* in_sizes, int n_in,
                              void* d_out, int out_size)
{
    const float* x       = (const float*)d_in[0];
    const float* rope_c  = (const float*)d_in[1];
    const float* rope_s  = (const float*)d_in[2];
    const float* wq      = (const float*)d_in[4];
    const float* wk      = (const float*)d_in[5];
    const float* wv      = (const float*)d_in[6];
    const float* wo      = (const float*)d_in[7];
    const float* qnw     = (const float*)d_in[8];
    const float* knw     = (const float*)d_in[9];
    float* out = (float*)d_out;

    float *q, *k, *v, *o;
    cudaGetSymbolAddress((void**)&q, g_q);
    cudaGetSymbolAddress((void**)&k, g_k);
    cudaGetSymbolAddress((void**)&v, g_v);
    cudaGetSymbolAddress((void**)&o, g_o);

    dim3 ggrid(DIM / TBN, TOK / TBM);  // (16, 64)
    gemm_tf32<<<ggrid, 256>>>(x, wq, q, TOK, DIM, DIM);
    gemm_tf32<<<ggrid, 256>>>(x, wk, k, TOK, DIM, DIM);
    gemm_tf32<<<ggrid, 256>>>(x, wv, v, TOK, DIM, DIM);

    dim3 ngrid(NH, TOK);
    rmsnorm_rope_kernel<<<ngrid, 128>>>(q, qnw, rope_c, rope_s);
    rmsnorm_rope_kernel<<<ngrid, 128>>>(k, knw, rope_c, rope_s);

    const int flash_smem = FLASH_SMEM_FLOATS * sizeof(float);
    cudaFuncSetAttribute(flash_tc, cudaFuncAttributeMaxDynamicSharedMemorySize,
                         flash_smem);
    dim3 fgrid(SS / FBQ, BB * NH);  // (16, 64)
    flash_tc<<<fgrid, 256, flash_smem>>>(q, k, v, o);

    gemm_tf32<<<ggrid, 256>>>(o, wo, out, TOK, DIM, DIM);
}

// round 6
// speedup vs baseline: 2.9937x; 1.0842x over previous
#include <cuda_runtime.h>
#include <math.h>
#include <stdint.h>

// Problem constants
#define BB   4
#define SS   2048
#define DIM  2048
#define NH   16
#define HD   128
#define TOK  (BB * SS)          // 8192
#define EPSF 1e-6f

// Scratch (device globals: allocation-free)
__device__ float g_q[(size_t)TOK * DIM];
__device__ float g_k[(size_t)TOK * DIM];
__device__ float g_v[(size_t)TOK * DIM];
__device__ float g_o[(size_t)TOK * DIM];

// ---------------------------------------------------------------------------
// Common helpers
// ---------------------------------------------------------------------------
__device__ __forceinline__ uint32_t f2tf(float f) {
    uint32_t o;
    asm("cvt.rna.tf32.f32 %0, %1;" : "=r"(o) : "f"(f));
    return o;
}

__device__ __forceinline__ void mma_tf32(float c[4], uint32_t a0, uint32_t a1,
                                         uint32_t a2, uint32_t a3,
                                         uint32_t b0, uint32_t b1) {
    asm volatile(
        "mma.sync.aligned.m16n8k8.row.col.f32.tf32.tf32.f32 "
        "{%0,%1,%2,%3}, {%4,%5,%6,%7}, {%8,%9}, {%0,%1,%2,%3};"
        : "+f"(c[0]), "+f"(c[1]), "+f"(c[2]), "+f"(c[3])
        : "r"(a0), "r"(a1), "r"(a2), "r"(a3), "r"(b0), "r"(b1));
}

__device__ __forceinline__ uint4 f4tf(float4 v) {
    uint4 u;
    u.x = f2tf(v.x); u.y = f2tf(v.y); u.z = f2tf(v.z); u.w = f2tf(v.w);
    return u;
}

// ---------------------------------------------------------------------------
// TF32 tensor-core GEMM (NT): C[m][n] = sum_k A[m][k] * B[n][k]
// CTA tile 128x256x16, 8 warps (2m x 4n), warp tile 64x64.
// Smem stride 20 words -> (20g + c) mod 32 is a bank permutation:
// conflict-free fragment loads. Double-buffered, register prefetch.
// ---------------------------------------------------------------------------
#define TBM 128
#define TBN 256
#define TBK 16
#define AST 20

// dynamic smem: As[2][128*20] + Bs[2][256*20] words
#define GEMM_SMEM_WORDS (2 * TBM * AST + 2 * TBN * AST)

__global__ __launch_bounds__(256) void gemm_tf32(const float* __restrict__ A,
                                                 const float* __restrict__ B,
                                                 float* __restrict__ C,
                                                 int M, int N, int K)
{
    extern __shared__ uint32_t smw[];
    uint32_t* As[2] = { smw, smw + TBM * AST };
    uint32_t* Bs[2] = { smw + 2 * TBM * AST, smw + 2 * TBM * AST + TBN * AST };

    const int bm = blockIdx.y * TBM;
    const int bn = blockIdx.x * TBN;
    const int tid = threadIdx.x;
    const int warp = tid >> 5;
    const int lane = tid & 31;
    const int g = lane >> 2;        // 0..7
    const int cth = lane & 3;       // 0..3
    const int wm = warp & 1;        // 64 rows each
    const int wn = warp >> 1;       // 64 cols each

    // loader mapping: thread covers rows (lr, lr+64[, +128, +192]), k-cols [lc,lc+4)
    const int lr = tid >> 2;             // 0..63
    const int lc = (tid & 3) * 4;        // 0,4,8,12
    const float* Ag = A + (size_t)(bm + lr) * K + lc;
    const float* Bg = B + (size_t)(bn + lr) * K + lc;

    float acc[4][8][4];
#pragma unroll
    for (int mi = 0; mi < 4; mi++)
#pragma unroll
        for (int ni = 0; ni < 8; ni++)
#pragma unroll
            for (int e = 0; e < 4; e++) acc[mi][ni][e] = 0.f;

    const int ntiles = K / TBK;

    // load tile 0
    float4 ra0 = *(const float4*)(Ag);
    float4 ra1 = *(const float4*)(Ag + (size_t)64 * K);
    float4 rb0 = *(const float4*)(Bg);
    float4 rb1 = *(const float4*)(Bg + (size_t)64 * K);
    float4 rb2 = *(const float4*)(Bg + (size_t)128 * K);
    float4 rb3 = *(const float4*)(Bg + (size_t)192 * K);
    {
        *(uint4*)(As[0] + lr * AST + lc) = f4tf(ra0);
        *(uint4*)(As[0] + (lr + 64) * AST + lc) = f4tf(ra1);
        *(uint4*)(Bs[0] + lr * AST + lc) = f4tf(rb0);
        *(uint4*)(Bs[0] + (lr + 64) * AST + lc) = f4tf(rb1);
        *(uint4*)(Bs[0] + (lr + 128) * AST + lc) = f4tf(rb2);
        *(uint4*)(Bs[0] + (lr + 192) * AST + lc) = f4tf(rb3);
    }
    __syncthreads();

    for (int t = 0; t < ntiles; t++) {
        // prefetch next tile into regs
        if (t + 1 < ntiles) {
            const int off = (t + 1) * TBK;
            ra0 = *(const float4*)(Ag + off);
            ra1 = *(const float4*)(Ag + (size_t)64 * K + off);
            rb0 = *(const float4*)(Bg + off);
            rb1 = *(const float4*)(Bg + (size_t)64 * K + off);
            rb2 = *(const float4*)(Bg + (size_t)128 * K + off);
            rb3 = *(const float4*)(Bg + (size_t)192 * K + off);
        }

        const uint32_t* as = As[t & 1];
        const uint32_t* bs = Bs[t & 1];

#pragma unroll
        for (int ks = 0; ks < TBK; ks += 8) {
            uint32_t a[4][4], b[8][2];
#pragma unroll
            for (int mi = 0; mi < 4; mi++) {
                const int rb = wm * 64 + mi * 16 + g;
                a[mi][0] = as[rb * AST + ks + cth];
                a[mi][1] = as[(rb + 8) * AST + ks + cth];
                a[mi][2] = as[rb * AST + ks + cth + 4];
                a[mi][3] = as[(rb + 8) * AST + ks + cth + 4];
            }
#pragma unroll
            for (int ni = 0; ni < 8; ni++) {
                const int cb = wn * 64 + ni * 8 + g;
                b[ni][0] = bs[cb * AST + ks + cth];
                b[ni][1] = bs[cb * AST + ks + cth + 4];
            }
#pragma unroll
            for (int mi = 0; mi < 4; mi++)
#pragma unroll
                for (int ni = 0; ni < 8; ni++)
                    mma_tf32(acc[mi][ni], a[mi][0], a[mi][1], a[mi][2], a[mi][3],
                             b[ni][0], b[ni][1]);
        }

        if (t + 1 < ntiles) {
            uint32_t* asn = As[(t + 1) & 1];
            uint32_t* bsn = Bs[(t + 1) & 1];
            *(uint4*)(asn + lr * AST + lc) = f4tf(ra0);
            *(uint4*)(asn + (lr + 64) * AST + lc) = f4tf(ra1);
            *(uint4*)(bsn + lr * AST + lc) = f4tf(rb0);
            *(uint4*)(bsn + (lr + 64) * AST + lc) = f4tf(rb1);
            *(uint4*)(bsn + (lr + 128) * AST + lc) = f4tf(rb2);
            *(uint4*)(bsn + (lr + 192) * AST + lc) = f4tf(rb3);
            __syncthreads();
        }
    }

    // Epilogue
#pragma unroll
    for (int mi = 0; mi < 4; mi++) {
        const int r0 = bm + wm * 64 + mi * 16 + g;
#pragma unroll
        for (int ni = 0; ni < 8; ni++) {
            const int col = bn + wn * 64 + ni * 8 + cth * 2;
            *(float2*)(C + (size_t)r0 * N + col) = make_float2(acc[mi][ni][0], acc[mi][ni][1]);
            *(float2*)(C + (size_t)(r0 + 8) * N + col) = make_float2(acc[mi][ni][2], acc[mi][ni][3]);
        }
    }
}

// ---------------------------------------------------------------------------
// Fused per-head RMSNorm + RoPE (rotate-half), q and k in one launch (grid.z).
// ---------------------------------------------------------------------------
__global__ __launch_bounds__(128) void rmsnorm_rope_kernel(float* __restrict__ qbuf,
                                                           float* __restrict__ kbuf,
                                                           const float* __restrict__ qw,
                                                           const float* __restrict__ kw,
                                                           const float* __restrict__ cos_t,
                                                           const float* __restrict__ sin_t)
{
    const int token = blockIdx.y;
    const int h = blockIdx.x;
    const int d = threadIdx.x;
    const int s = token & (SS - 1);

    float* buf = blockIdx.z ? kbuf : qbuf;
    const float* w = blockIdx.z ? kw : qw;

    float* ptr = buf + (size_t)token * DIM + h * HD;
    float v = ptr[d];

    float sq = v * v;
#pragma unroll
    for (int off = 16; off > 0; off >>= 1)
        sq += __shfl_xor_sync(0xffffffffu, sq, off);

    __shared__ float wsum[4];
    const int wid = d >> 5;
    if ((d & 31) == 0) wsum[wid] = sq;
    __syncthreads();
    float tot = wsum[0] + wsum[1] + wsum[2] + wsum[3];

    float rms = rsqrtf(tot * (1.0f / HD) + EPSF);
    float xn = v * rms * w[d];

    __shared__ float xs[HD];
    xs[d] = xn;
    __syncthreads();

    float rot = (d < 64) ? -xs[d + 64] : xs[d - 64];
    ptr[d] = xn * cos_t[s * HD + d] + rot * sin_t[s * HD + d];
}

// ---------------------------------------------------------------------------
// Causal flash attention with tf32 mma.sync tensor cores. (unchanged R5)
// BQ=128, BK=64, HD=128. 256 threads = 8 warps; warp w owns q-rows w*16..+15.
// ---------------------------------------------------------------------------
#define FBQ 128
#define FBK 64
#define QSTR 132
#define KSTR 132
#define VSTR 136
#define PSTR 68

#define FLASH_SMEM_FLOATS (FBQ * QSTR + FBK * KSTR + FBK * VSTR + FBQ * PSTR)

__global__ __launch_bounds__(256) void flash_tc(const float* __restrict__ q,
                                                const float* __restrict__ k,
                                                const float* __restrict__ v,
                                                float* __restrict__ o)
{
    extern __shared__ float smf[];
    float* Qs = smf;                    // tf32 bits
    float* Ks = Qs + FBQ * QSTR;
    float* Vs = Ks + FBK * KSTR;
    float* Ps = Vs + FBK * VSTR;

    const int q0 = blockIdx.x * FBQ;
    const int bh = blockIdx.y;
    const int b = bh >> 4;
    const int h = bh & 15;
    const size_t base = (size_t)b * SS * DIM + (size_t)h * HD;

    const int tid = threadIdx.x;
    const int w = tid >> 5;
    const int lane = tid & 31;
    const int g = lane >> 2;          // 0..7
    const int cth = lane & 3;         // 0..3
    const float scale = 0.08838834764831845f;  // 1/sqrt(128)

#pragma unroll
    for (int p = 0; p < 16; p++) {
        int idx = tid + p * 256;
        int r = idx >> 5;
        int c4 = (idx & 31) * 4;
        float4 qv = *(const float4*)(q + base + (size_t)(q0 + r) * DIM + c4);
        uint4 u;
        u.x = f2tf(qv.x * scale); u.y = f2tf(qv.y * scale);
        u.z = f2tf(qv.z * scale); u.w = f2tf(qv.w * scale);
        *(uint4*)(Qs + r * QSTR + c4) = u;
    }

    float m0 = -INFINITY, m1 = -INFINITY, l0 = 0.f, l1 = 0.f;
    float acc[16][4];
#pragma unroll
    for (int nb = 0; nb < 16; nb++)
#pragma unroll
        for (int e = 0; e < 4; e++) acc[nb][e] = 0.f;

    const int rowg = q0 + w * 16 + g;
    float* Qw = Qs + (w * 16) * QSTR;
    float* Pw = Ps + (w * 16) * PSTR;

    const int nkb = q0 / FBK + 2;
    for (int kb = 0; kb < nkb; kb++) {
        const int k0 = kb * FBK;
        __syncthreads();

#pragma unroll
        for (int p = 0; p < 8; p++) {
            int idx = tid + p * 256;
            int r = idx >> 5;
            int c4 = (idx & 31) * 4;
            float4 kv = *(const float4*)(k + base + (size_t)(k0 + r) * DIM + c4);
            uint4 uk;
            uk.x = f2tf(kv.x); uk.y = f2tf(kv.y); uk.z = f2tf(kv.z); uk.w = f2tf(kv.w);
            *(uint4*)(Ks + r * KSTR + c4) = uk;
            float4 vv = *(const float4*)(v + base + (size_t)(k0 + r) * DIM + c4);
            uint4 uv;
            uv.x = f2tf(vv.x); uv.y = f2tf(vv.y); uv.z = f2tf(vv.z); uv.w = f2tf(vv.w);
            *(uint4*)(Vs + r * VSTR + c4) = uv;
        }
        __syncthreads();

        if (k0 > q0 + w * 16 + 15) continue;

        float c[8][4];
#pragma unroll
        for (int nb = 0; nb < 8; nb++)
#pragma unroll
            for (int e = 0; e < 4; e++) c[nb][e] = 0.f;

#pragma unroll 4
        for (int kc = 0; kc < 16; kc++) {
            const int kcol = kc * 8 + cth;
            uint32_t a0 = __float_as_uint(Qw[g * QSTR + kcol]);
            uint32_t a1 = __float_as_uint(Qw[(g + 8) * QSTR + kcol]);
            uint32_t a2 = __float_as_uint(Qw[g * QSTR + kcol + 4]);
            uint32_t a3 = __float_as_uint(Qw[(g + 8) * QSTR + kcol + 4]);
#pragma unroll
            for (int nb = 0; nb < 8; nb++) {
                uint32_t b0 = __float_as_uint(Ks[(nb * 8 + g) * KSTR + kcol]);
                uint32_t b1 = __float_as_uint(Ks[(nb * 8 + g) * KSTR + kcol + 4]);
                mma_tf32(c[nb], a0, a1, a2, a3, b0, b1);
            }
        }

        if (k0 + FBK - 1 > rowg) {
#pragma unroll
            for (int nb = 0; nb < 8; nb++) {
                const int col = k0 + nb * 8 + 2 * cth;
                if (col > rowg)         c[nb][0] = -INFINITY;
                if (col + 1 > rowg)     c[nb][1] = -INFINITY;
                if (col > rowg + 8)     c[nb][2] = -INFINITY;
                if (col + 1 > rowg + 8) c[nb][3] = -INFINITY;
            }
        }

        float mx0 = -INFINITY, mx1 = -INFINITY;
#pragma unroll
        for (int nb = 0; nb < 8; nb++) {
            mx0 = fmaxf(mx0, fmaxf(c[nb][0], c[nb][1]));
            mx1 = fmaxf(mx1, fmaxf(c[nb][2], c[nb][3]));
        }
        mx0 = fmaxf(mx0, __shfl_xor_sync(0xffffffffu, mx0, 1));
        mx0 = fmaxf(mx0, __shfl_xor_sync(0xffffffffu, mx0, 2));
        mx1 = fmaxf(mx1, __shfl_xor_sync(0xffffffffu, mx1, 1));
        mx1 = fmaxf(mx1, __shfl_xor_sync(0xffffffffu, mx1, 2));

        const float mn0 = fmaxf(m0, mx0);
        const float mn1 = fmaxf(m1, mx1);
        float rs0 = 0.f, rs1 = 0.f;
#pragma unroll
        for (int nb = 0; nb < 8; nb++) {
            c[nb][0] = __expf(c[nb][0] - mn0);
            c[nb][1] = __expf(c[nb][1] - mn0);
            c[nb][2] = __expf(c[nb][2] - mn1);
            c[nb][3] = __expf(c[nb][3] - mn1);
            rs0 += c[nb][0] + c[nb][1];
            rs1 += c[nb][2] + c[nb][3];
        }
        rs0 += __shfl_xor_sync(0xffffffffu, rs0, 1);
        rs0 += __shfl_xor_sync(0xffffffffu, rs0, 2);
        rs1 += __shfl_xor_sync(0xffffffffu, rs1, 1);
        rs1 += __shfl_xor_sync(0xffffffffu, rs1, 2);

        const float al0 = __expf(m0 - mn0);
        const float al1 = __expf(m1 - mn1);
        l0 = l0 * al0 + rs0;
        l1 = l1 * al1 + rs1;
        m0 = mn0;
        m1 = mn1;

#pragma unroll
        for (int nb = 0; nb < 16; nb++) {
            acc[nb][0] *= al0; acc[nb][1] *= al0;
            acc[nb][2] *= al1; acc[nb][3] *= al1;
        }

#pragma unroll
        for (int nb = 0; nb < 8; nb++) {
            const int colb = nb * 8 + 2 * cth;
            *(uint2*)(Pw + g * PSTR + colb) = make_uint2(f2tf(c[nb][0]), f2tf(c[nb][1]));
            *(uint2*)(Pw + (g + 8) * PSTR + colb) = make_uint2(f2tf(c[nb][2]), f2tf(c[nb][3]));
        }
        __syncwarp();

#pragma unroll 2
        for (int kc = 0; kc < 8; kc++) {
            const int kr = kc * 8 + cth;
            uint32_t a0 = __float_as_uint(Pw[g * PSTR + kr]);
            uint32_t a1 = __float_as_uint(Pw[(g + 8) * PSTR + kr]);
            uint32_t a2 = __float_as_uint(Pw[g * PSTR + kr + 4]);
            uint32_t a3 = __float_as_uint(Pw[(g + 8) * PSTR + kr + 4]);
#pragma unroll
            for (int nb = 0; nb < 16; nb++) {
                uint32_t b0 = __float_as_uint(Vs[kr * VSTR + nb * 8 + g]);
                uint32_t b1 = __float_as_uint(Vs[(kr + 4) * VSTR + nb * 8 + g]);
                mma_tf32(acc[nb], a0, a1, a2, a3, b0, b1);
            }
        }
        __syncwarp();
    }

    const float il0 = 1.0f / l0;
    const float il1 = 1.0f / l1;
    const size_t r0 = (size_t)rowg;
    const size_t r1 = (size_t)(rowg + 8);
#pragma unroll
    for (int nb = 0; nb < 16; nb++) {
        const int col = nb * 8 + 2 * cth;
        *(float2*)(o + base + r0 * DIM + col) = make_float2(acc[nb][0] * il0, acc[nb][1] * il0);
        *(float2*)(o + base + r1 * DIM + col) = make_float2(acc[nb][2] * il1, acc[nb][3] * il1);
    }
}

// ---------------------------------------------------------------------------
// Launch
// Inputs: 0=x 1=rope_cos 2=rope_sin 3=attn_mask 4=wq 5=wk 6=wv 7=wo
//         8=q_norm_w 9=k_norm_w
// ---------------------------------------------------------------------------
extern "C" void kernel_launch(void* const* d_in, const int* in_sizes, int n_in,
                              void* d_out, int out_size)
{
    const float* x       = (const float*)d_in[0];
    const float* rope_c  = (const float*)d_in[1];
    const float* rope_s  = (const float*)d_in[2];
    const float* wq      = (const float*)d_in[4];
    const float* wk      = (const float*)d_in[5];
    const float* wv      = (const float*)d_in[6];
    const float* wo      = (const float*)d_in[7];
    const float* qnw     = (const float*)d_in[8];
    const float* knw     = (const float*)d_in[9];
    float* out = (float*)d_out;

    float *q, *k, *v, *o;
    cudaGetSymbolAddress((void**)&q, g_q);
    cudaGetSymbolAddress((void**)&k, g_k);
    cudaGetSymbolAddress((void**)&v, g_v);
    cudaGetSymbolAddress((void**)&o, g_o);

    const int gemm_smem = GEMM_SMEM_WORDS * sizeof(uint32_t);  // ~60 KB
    cudaFuncSetAttribute(gemm_tf32, cudaFuncAttributeMaxDynamicSharedMemorySize,
                         gemm_smem);

    dim3 ggrid(DIM / TBN, TOK / TBM);  // (8, 64)
    gemm_tf32<<<ggrid, 256, gemm_smem>>>(x, wq, q, TOK, DIM, DIM);
    gemm_tf32<<<ggrid, 256, gemm_smem>>>(x, wk, k, TOK, DIM, DIM);
    gemm_tf32<<<ggrid, 256, gemm_smem>>>(x, wv, v, TOK, DIM, DIM);

    dim3 ngrid(NH, TOK, 2);
    rmsnorm_rope_kernel<<<ngrid, 128>>>(q, k, qnw, knw, rope_c, rope_s);

    const int flash_smem = FLASH_SMEM_FLOATS * sizeof(float);
    cudaFuncSetAttribute(flash_tc, cudaFuncAttributeMaxDynamicSharedMemorySize,
                         flash_smem);
    dim3 fgrid(SS / FBQ, BB * NH);  // (16, 64)
    flash_tc<<<fgrid, 256, flash_smem>>>(q, k, v, o);

    gemm_tf32<<<ggrid, 256, gemm_smem>>>(o, wo, out, TOK, DIM, DIM);
}

// round 8
// speedup vs baseline: 3.9762x; 1.3282x over previous
#include <cuda_runtime.h>
#include <cuda_fp16.h>
#include <math.h>
#include <stdint.h>

// Problem constants
#define BB   4
#define SS   2048
#define DIM  2048
#define NH   16
#define HD   128
#define TOK  (BB * SS)          // 8192
#define EPSF 1e-6f

// Scratch (device globals: allocation-free)
__device__ float g_q[(size_t)TOK * DIM];
__device__ float g_k[(size_t)TOK * DIM];
__device__ float g_v[(size_t)TOK * DIM];
__device__ float g_o[(size_t)TOK * DIM];

// ---------------------------------------------------------------------------
// Common helpers
// ---------------------------------------------------------------------------
__device__ __forceinline__ uint32_t f2h2(float a, float b) {
    __half2 h = __floats2half2_rn(a, b);   // x=a (low), y=b (high)
    return *(uint32_t*)&h;
}

__device__ __forceinline__ uint2 f4h(float4 v) {
    return make_uint2(f2h2(v.x, v.y), f2h2(v.z, v.w));
}

__device__ __forceinline__ void mma_f16(float c[4], uint32_t a0, uint32_t a1,
                                        uint32_t a2, uint32_t a3,
                                        uint32_t b0, uint32_t b1) {
    asm volatile(
        "mma.sync.aligned.m16n8k16.row.col.f32.f16.f16.f32 "
        "{%0,%1,%2,%3}, {%4,%5,%6,%7}, {%8,%9}, {%0,%1,%2,%3};"
        : "+f"(c[0]), "+f"(c[1]), "+f"(c[2]), "+f"(c[3])
        : "r"(a0), "r"(a1), "r"(a2), "r"(a3), "r"(b0), "r"(b1));
}

// ---------------------------------------------------------------------------
// FP16 tensor-core GEMM (NT): C[m][n] = sum_k A[m][k] * B[n][k]
// CTA tile 128x256x32, 8 warps (2m x 4n), warp tile 64x64.
// Smem: half2-packed k-pairs, row stride 20 half2 (16 used + 4 pad).
// Bank check: (20g + c) mod 32 -> {0,20,8,28,16,4,24,12}+cth : all distinct.
// Double-buffered, register prefetch.
// ---------------------------------------------------------------------------
#define TBM 128
#define TBN 256
#define TBK 32
#define AST2 20   // half2 per row

#define GEMM_SMEM_WORDS (2 * (TBM + TBN) * AST2)   // 15360 words = 60 KB

__global__ __launch_bounds__(256) void gemm_f16(const float* __restrict__ A,
                                                const float* __restrict__ B,
                                                float* __restrict__ C,
                                                int M, int N, int K)
{
    extern __shared__ uint32_t smw[];
    uint32_t* As[2] = { smw, smw + TBM * AST2 };
    uint32_t* Bs[2] = { smw + 2 * TBM * AST2, smw + 2 * TBM * AST2 + TBN * AST2 };

    const int bm = blockIdx.y * TBM;
    const int bn = blockIdx.x * TBN;
    const int tid = threadIdx.x;
    const int warp = tid >> 5;
    const int lane = tid & 31;
    const int g = lane >> 2;        // 0..7
    const int cth = lane & 3;       // 0..3
    const int wm = warp & 1;        // 64 rows each
    const int wn = warp >> 1;       // 64 cols each

    // loader: thread covers rows (tid>>3 + 32p), k-floats [(tid&7)*4, +4)
    const int ar = tid >> 3;            // 0..31
    const int ac = (tid & 7) * 4;       // float col 0..28
    const int ah = (tid & 7) * 2;       // half2 col

    float acc[4][8][4];
#pragma unroll
    for (int mi = 0; mi < 4; mi++)
#pragma unroll
        for (int ni = 0; ni < 8; ni++)
#pragma unroll
            for (int e = 0; e < 4; e++) acc[mi][ni][e] = 0.f;

    const int ntiles = K / TBK;   // 64

    float4 ra[4], rb[8];
#pragma unroll
    for (int p = 0; p < 4; p++)
        ra[p] = *(const float4*)(A + (size_t)(bm + ar + 32 * p) * K + ac);
#pragma unroll
    for (int p = 0; p < 8; p++)
        rb[p] = *(const float4*)(B + (size_t)(bn + ar + 32 * p) * K + ac);
#pragma unroll
    for (int p = 0; p < 4; p++)
        *(uint2*)(As[0] + (ar + 32 * p) * AST2 + ah) = f4h(ra[p]);
#pragma unroll
    for (int p = 0; p < 8; p++)
        *(uint2*)(Bs[0] + (ar + 32 * p) * AST2 + ah) = f4h(rb[p]);
    __syncthreads();

    for (int t = 0; t < ntiles; t++) {
        if (t + 1 < ntiles) {
            const int off = (t + 1) * TBK + ac;
#pragma unroll
            for (int p = 0; p < 4; p++)
                ra[p] = *(const float4*)(A + (size_t)(bm + ar + 32 * p) * K + off);
#pragma unroll
            for (int p = 0; p < 8; p++)
                rb[p] = *(const float4*)(B + (size_t)(bn + ar + 32 * p) * K + off);
        }

        const uint32_t* as = As[t & 1];
        const uint32_t* bs = Bs[t & 1];

#pragma unroll
        for (int kch = 0; kch < 2; kch++) {
            const int kb = kch * 8;
            uint32_t a[4][4], b[8][2];
#pragma unroll
            for (int mi = 0; mi < 4; mi++) {
                const int rb0 = wm * 64 + mi * 16 + g;
                a[mi][0] = as[rb0 * AST2 + kb + cth];
                a[mi][1] = as[(rb0 + 8) * AST2 + kb + cth];
                a[mi][2] = as[rb0 * AST2 + kb + cth + 4];
                a[mi][3] = as[(rb0 + 8) * AST2 + kb + cth + 4];
            }
#pragma unroll
            for (int ni = 0; ni < 8; ni++) {
                const int cb = wn * 64 + ni * 8 + g;
                b[ni][0] = bs[cb * AST2 + kb + cth];
                b[ni][1] = bs[cb * AST2 + kb + cth + 4];
            }
#pragma unroll
            for (int mi = 0; mi < 4; mi++)
#pragma unroll
                for (int ni = 0; ni < 8; ni++)
                    mma_f16(acc[mi][ni], a[mi][0], a[mi][1], a[mi][2], a[mi][3],
                            b[ni][0], b[ni][1]);
        }

        if (t + 1 < ntiles) {
            uint32_t* asn = As[(t + 1) & 1];
            uint32_t* bsn = Bs[(t + 1) & 1];
#pragma unroll
            for (int p = 0; p < 4; p++)
                *(uint2*)(asn + (ar + 32 * p) * AST2 + ah) = f4h(ra[p]);
#pragma unroll
            for (int p = 0; p < 8; p++)
                *(uint2*)(bsn + (ar + 32 * p) * AST2 + ah) = f4h(rb[p]);
            __syncthreads();
        }
    }

    // Epilogue
#pragma unroll
    for (int mi = 0; mi < 4; mi++) {
        const int r0 = bm + wm * 64 + mi * 16 + g;
#pragma unroll
        for (int ni = 0; ni < 8; ni++) {
            const int col = bn + wn * 64 + ni * 8 + cth * 2;
            *(float2*)(C + (size_t)r0 * N + col) = make_float2(acc[mi][ni][0], acc[mi][ni][1]);
            *(float2*)(C + (size_t)(r0 + 8) * N + col) = make_float2(acc[mi][ni][2], acc[mi][ni][3]);
        }
    }
}

// ---------------------------------------------------------------------------
// Fused per-head RMSNorm + RoPE (rotate-half), q and k in one launch (grid.z).
// ---------------------------------------------------------------------------
__global__ __launch_bounds__(128) void rmsnorm_rope_kernel(float* __restrict__ qbuf,
                                                           float* __restrict__ kbuf,
                                                           const float* __restrict__ qw,
                                                           const float* __restrict__ kw,
                                                           const float* __restrict__ cos_t,
                                                           const float* __restrict__ sin_t)
{
    const int token = blockIdx.y;
    const int h = blockIdx.x;
    const int d = threadIdx.x;
    const int s = token & (SS - 1);

    float* buf = blockIdx.z ? kbuf : qbuf;
    const float* w = blockIdx.z ? kw : qw;

    float* ptr = buf + (size_t)token * DIM + h * HD;
    float v = ptr[d];

    float sq = v * v;
#pragma unroll
    for (int off = 16; off > 0; off >>= 1)
        sq += __shfl_xor_sync(0xffffffffu, sq, off);

    __shared__ float wsum[4];
    const int wid = d >> 5;
    if ((d & 31) == 0) wsum[wid] = sq;
    __syncthreads();
    float tot = wsum[0] + wsum[1] + wsum[2] + wsum[3];

    float rms = rsqrtf(tot * (1.0f / HD) + EPSF);
    float xn = v * rms * w[d];

    __shared__ float xs[HD];
    xs[d] = xn;
    __syncthreads();

    float rot = (d < 64) ? -xs[d + 64] : xs[d - 64];
    ptr[d] = xn * cos_t[s * HD + d] + rot * sin_t[s * HD + d];
}

// ---------------------------------------------------------------------------
// Causal flash attention with fp16 mma.sync (m16n8k16).
// BQ=128, BK=64, HD=128. 256 threads = 8 warps; warp w owns q-rows w*16..+15.
// Smem (half2 units): Q/K stride 68 (64 used), Vt (transposed: [hd][key])
// stride 36 (32 used), P stride 36. Bank checks: fragment loads hit
// (4g + cth) mod 32 -> conflict-free.
// ---------------------------------------------------------------------------
#define FBQ 128
#define FBK 64
#define QS2 68   // half2 per Q/K row
#define VT2 36   // half2 per Vt row (keys)
#define PS2 36   // half2 per P row

#define FLASH_SMEM_WORDS (FBQ * QS2 + FBK * QS2 + HD * VT2 + FBQ * PS2)

__global__ __launch_bounds__(256) void flash_f16(const float* __restrict__ q,
                                                 const float* __restrict__ k,
                                                 const float* __restrict__ v,
                                                 float* __restrict__ o)
{
    extern __shared__ uint32_t smh[];
    uint32_t* Qs2 = smh;                       // 128 x 68
    uint32_t* Ks2 = Qs2 + FBQ * QS2;           // 64 x 68
    uint32_t* Vt2 = Ks2 + FBK * QS2;           // 128 x 36  (row = hd, col = key)
    uint32_t* Ps2 = Vt2 + HD * VT2;            // 128 x 36
    __half*  VtH = (__half*)Vt2;

    const int q0 = blockIdx.x * FBQ;
    const int bh = blockIdx.y;
    const int b = bh >> 4;
    const int h = bh & 15;
    const size_t base = (size_t)b * SS * DIM + (size_t)h * HD;

    const int tid = threadIdx.x;
    const int w = tid >> 5;
    const int lane = tid & 31;
    const int g = lane >> 2;          // 0..7
    const int cth = lane & 3;         // 0..3
    const float scale = 0.08838834764831845f;  // 1/sqrt(128)

    // ---- Load Q tile (scaled, fp16). 128x128 floats = 4096 float4 ----
#pragma unroll
    for (int p = 0; p < 16; p++) {
        int idx = tid + p * 256;
        int r = idx >> 5;
        int c32 = idx & 31;
        float4 qv = *(const float4*)(q + base + (size_t)(q0 + r) * DIM + c32 * 4);
        *(uint2*)(Qs2 + r * QS2 + c32 * 2) =
            make_uint2(f2h2(qv.x * scale, qv.y * scale), f2h2(qv.z * scale, qv.w * scale));
    }

    float m0 = -INFINITY, m1 = -INFINITY, l0 = 0.f, l1 = 0.f;
    float acc[16][4];
#pragma unroll
    for (int nb = 0; nb < 16; nb++)
#pragma unroll
        for (int e = 0; e < 4; e++) acc[nb][e] = 0.f;

    const int rowg = q0 + w * 16 + g;
    uint32_t* Qw2 = Qs2 + (w * 16) * QS2;
    uint32_t* Pw2 = Ps2 + (w * 16) * PS2;

    const int nkb = q0 / FBK + 2;
    for (int kb = 0; kb < nkb; kb++) {
        const int k0 = kb * FBK;
        __syncthreads();   // prior-iter smem reads done

        // ---- K tile: 64x128 floats, rows = keys ----
#pragma unroll
        for (int p = 0; p < 8; p++) {
            int idx = tid + p * 256;
            int r = idx >> 5;
            int c32 = idx & 31;
            float4 kv = *(const float4*)(k + base + (size_t)(k0 + r) * DIM + c32 * 4);
            *(uint2*)(Ks2 + r * QS2 + c32 * 2) =
                make_uint2(f2h2(kv.x, kv.y), f2h2(kv.z, kv.w));
        }
        // ---- V tile TRANSPOSED: Vt[hd][key]. lane<->key so STS coalesce ----
#pragma unroll
        for (int p = 0; p < 8; p++) {
            int idx = tid + p * 256;
            int key = idx & 63;
            int hd4 = (idx >> 6) * 4;
            float4 vv = *(const float4*)(v + base + (size_t)(k0 + key) * DIM + hd4);
            VtH[(hd4 + 0) * (2 * VT2) + key] = __float2half_rn(vv.x);
            VtH[(hd4 + 1) * (2 * VT2) + key] = __float2half_rn(vv.y);
            VtH[(hd4 + 2) * (2 * VT2) + key] = __float2half_rn(vv.z);
            VtH[(hd4 + 3) * (2 * VT2) + key] = __float2half_rn(vv.w);
        }
        __syncthreads();

        if (k0 > q0 + w * 16 + 15) continue;   // fully-masked tile for this warp

        // ---- S = Q K^T : 8 k-chunks (k=16) x 8 n-blocks ----
        float c[8][4];
#pragma unroll
        for (int nb = 0; nb < 8; nb++)
#pragma unroll
            for (int e = 0; e < 4; e++) c[nb][e] = 0.f;

#pragma unroll 2
        for (int kc = 0; kc < 8; kc++) {
            const int kh = kc * 8;
            uint32_t a0 = Qw2[g * QS2 + kh + cth];
            uint32_t a1 = Qw2[(g + 8) * QS2 + kh + cth];
            uint32_t a2 = Qw2[g * QS2 + kh + cth + 4];
            uint32_t a3 = Qw2[(g + 8) * QS2 + kh + cth + 4];
#pragma unroll
            for (int nb = 0; nb < 8; nb++) {
                const int n = nb * 8 + g;
                uint32_t b0 = Ks2[n * QS2 + kh + cth];
                uint32_t b1 = Ks2[n * QS2 + kh + cth + 4];
                mma_f16(c[nb], a0, a1, a2, a3, b0, b1);
            }
        }

        // ---- causal mask (near-diagonal tiles only) ----
        if (k0 + FBK - 1 > rowg) {
#pragma unroll
            for (int nb = 0; nb < 8; nb++) {
                const int col = k0 + nb * 8 + 2 * cth;
                if (col > rowg)         c[nb][0] = -INFINITY;
                if (col + 1 > rowg)     c[nb][1] = -INFINITY;
                if (col > rowg + 8)     c[nb][2] = -INFINITY;
                if (col + 1 > rowg + 8) c[nb][3] = -INFINITY;
            }
        }

        // ---- online softmax (2 quad shuffles per row stat) ----
        float mx0 = -INFINITY, mx1 = -INFINITY;
#pragma unroll
        for (int nb = 0; nb < 8; nb++) {
            mx0 = fmaxf(mx0, fmaxf(c[nb][0], c[nb][1]));
            mx1 = fmaxf(mx1, fmaxf(c[nb][2], c[nb][3]));
        }
        mx0 = fmaxf(mx0, __shfl_xor_sync(0xffffffffu, mx0, 1));
        mx0 = fmaxf(mx0, __shfl_xor_sync(0xffffffffu, mx0, 2));
        mx1 = fmaxf(mx1, __shfl_xor_sync(0xffffffffu, mx1, 1));
        mx1 = fmaxf(mx1, __shfl_xor_sync(0xffffffffu, mx1, 2));

        const float mn0 = fmaxf(m0, mx0);
        const float mn1 = fmaxf(m1, mx1);
        float rs0 = 0.f, rs1 = 0.f;
#pragma unroll
        for (int nb = 0; nb < 8; nb++) {
            c[nb][0] = __expf(c[nb][0] - mn0);
            c[nb][1] = __expf(c[nb][1] - mn0);
            c[nb][2] = __expf(c[nb][2] - mn1);
            c[nb][3] = __expf(c[nb][3] - mn1);
            rs0 += c[nb][0] + c[nb][1];
            rs1 += c[nb][2] + c[nb][3];
        }
        rs0 += __shfl_xor_sync(0xffffffffu, rs0, 1);
        rs0 += __shfl_xor_sync(0xffffffffu, rs0, 2);
        rs1 += __shfl_xor_sync(0xffffffffu, rs1, 1);
        rs1 += __shfl_xor_sync(0xffffffffu, rs1, 2);

        const float al0 = __expf(m0 - mn0);
        const float al1 = __expf(m1 - mn1);
        l0 = l0 * al0 + rs0;
        l1 = l1 * al1 + rs1;
        m0 = mn0;
        m1 = mn1;

#pragma unroll
        for (int nb = 0; nb < 16; nb++) {
            acc[nb][0] *= al0; acc[nb][1] *= al0;
            acc[nb][2] *= al1; acc[nb][3] *= al1;
        }

        // ---- stage P (fp16) in per-warp strip ----
#pragma unroll
        for (int nb = 0; nb < 8; nb++) {
            Pw2[g * PS2 + nb * 4 + cth]       = f2h2(c[nb][0], c[nb][1]);
            Pw2[(g + 8) * PS2 + nb * 4 + cth] = f2h2(c[nb][2], c[nb][3]);
        }
        __syncwarp();

        // ---- O += P V : 4 k-chunks (k=16 keys) x 16 n-blocks ----
#pragma unroll
        for (int kc = 0; kc < 4; kc++) {
            const int kh = kc * 8;
            uint32_t a0 = Pw2[g * PS2 + kh + cth];
            uint32_t a1 = Pw2[(g + 8) * PS2 + kh + cth];
            uint32_t a2 = Pw2[g * PS2 + kh + cth + 4];
            uint32_t a3 = Pw2[(g + 8) * PS2 + kh + cth + 4];
#pragma unroll
            for (int nb = 0; nb < 16; nb++) {
                const int n = nb * 8 + g;
                uint32_t b0 = Vt2[n * VT2 + kh + cth];
                uint32_t b1 = Vt2[n * VT2 + kh + cth + 4];
                mma_f16(acc[nb], a0, a1, a2, a3, b0, b1);
            }
        }
        __syncwarp();
    }

    // ---- epilogue ----
    const float il0 = 1.0f / l0;
    const float il1 = 1.0f / l1;
    const size_t r0 = (size_t)rowg;
    const size_t r1 = (size_t)(rowg + 8);
#pragma unroll
    for (int nb = 0; nb < 16; nb++) {
        const int col = nb * 8 + 2 * cth;
        *(float2*)(o + base + r0 * DIM + col) = make_float2(acc[nb][0] * il0, acc[nb][1] * il0);
        *(float2*)(o + base + r1 * DIM + col) = make_float2(acc[nb][2] * il1, acc[nb][3] * il1);
    }
}

// ---------------------------------------------------------------------------
// Launch
// Inputs: 0=x 1=rope_cos 2=rope_sin 3=attn_mask 4=wq 5=wk 6=wv 7=wo
//         8=q_norm_w 9=k_norm_w
// ---------------------------------------------------------------------------
extern "C" void kernel_launch(void* const* d_in, const int* in_sizes, int n_in,
                              void* d_out, int out_size)
{
    const float* x       = (const float*)d_in[0];
    const float* rope_c  = (const float*)d_in[1];
    const float* rope_s  = (const float*)d_in[2];
    const float* wq      = (const float*)d_in[4];
    const float* wk      = (const float*)d_in[5];
    const float* wv      = (const float*)d_in[6];
    const float* wo      = (const float*)d_in[7];
    const float* qnw     = (const float*)d_in[8];
    const float* knw     = (const float*)d_in[9];
    float* out = (float*)d_out;

    float *q, *k, *v, *o;
    cudaGetSymbolAddress((void**)&q, g_q);
    cudaGetSymbolAddress((void**)&k, g_k);
    cudaGetSymbolAddress((void**)&v, g_v);
    cudaGetSymbolAddress((void**)&o, g_o);

    const int gemm_smem = GEMM_SMEM_WORDS * sizeof(uint32_t);  // 60 KB
    cudaFuncSetAttribute(gemm_f16, cudaFuncAttributeMaxDynamicSharedMemorySize,
                         gemm_smem);

    dim3 ggrid(DIM / TBN, TOK / TBM);  // (8, 64)
    gemm_f16<<<ggrid, 256, gemm_smem>>>(x, wq, q, TOK, DIM, DIM);
    gemm_f16<<<ggrid, 256, gemm_smem>>>(x, wk, k, TOK, DIM, DIM);
    gemm_f16<<<ggrid, 256, gemm_smem>>>(x, wv, v, TOK, DIM, DIM);

    dim3 ngrid(NH, TOK, 2);
    rmsnorm_rope_kernel<<<ngrid, 128>>>(q, k, qnw, knw, rope_c, rope_s);

    const int flash_smem = FLASH_SMEM_WORDS * sizeof(uint32_t);  // ~89 KB
    cudaFuncSetAttribute(flash_f16, cudaFuncAttributeMaxDynamicSharedMemorySize,
                         flash_smem);
    dim3 fgrid(SS / FBQ, BB * NH);  // (16, 64)
    flash_f16<<<fgrid, 256, flash_smem>>>(q, k, v, o);

    gemm_f16<<<ggrid, 256, gemm_smem>>>(o, wo, out, TOK, DIM, DIM);
}

// round 9
// speedup vs baseline: 4.9523x; 1.2455x over previous
#include <cuda_runtime.h>
#include <cuda_fp16.h>
#include <math.h>
#include <stdint.h>

// Problem constants
#define BB   4
#define SS   2048
#define DIM  2048
#define NH   16
#define HD   128
#define TOK  (BB * SS)          // 8192
#define EPSF 1e-6f

// Scratch (device globals: allocation-free)
__device__ float  g_qf[(size_t)TOK * DIM];
__device__ float  g_kf[(size_t)TOK * DIM];
__device__ __half g_xh[(size_t)TOK * DIM];
__device__ __half g_qh[(size_t)TOK * DIM];
__device__ __half g_kh[(size_t)TOK * DIM];
__device__ __half g_vh[(size_t)TOK * DIM];
__device__ __half g_oh[(size_t)TOK * DIM];
__device__ __half g_wqh[(size_t)DIM * DIM];
__device__ __half g_wkh[(size_t)DIM * DIM];
__device__ __half g_wvh[(size_t)DIM * DIM];
__device__ __half g_woh[(size_t)DIM * DIM];

// ---------------------------------------------------------------------------
// Common helpers
// ---------------------------------------------------------------------------
__device__ __forceinline__ uint32_t f2h2(float a, float b) {
    __half2 h = __floats2half2_rn(a, b);
    return *(uint32_t*)&h;
}

__device__ __forceinline__ uint2 f4h(float4 v) {
    return make_uint2(f2h2(v.x, v.y), f2h2(v.z, v.w));
}

__device__ __forceinline__ void mma_f16(float c[4], uint32_t a0, uint32_t a1,
                                        uint32_t a2, uint32_t a3,
                                        uint32_t b0, uint32_t b1) {
    asm volatile(
        "mma.sync.aligned.m16n8k16.row.col.f32.f16.f16.f32 "
        "{%0,%1,%2,%3}, {%4,%5,%6,%7}, {%8,%9}, {%0,%1,%2,%3};"
        : "+f"(c[0]), "+f"(c[1]), "+f"(c[2]), "+f"(c[3])
        : "r"(a0), "r"(a1), "r"(a2), "r"(a3), "r"(b0), "r"(b1));
}

// ---------------------------------------------------------------------------
// fp32 -> fp16 convert (elementwise, vectorized)
// ---------------------------------------------------------------------------
__global__ __launch_bounds__(256) void f2h_kernel(const float* __restrict__ src,
                                                  __half* __restrict__ dst, int n)
{
    int i = (blockIdx.x * 256 + threadIdx.x) * 4;
    if (i < n) {
        float4 v = *(const float4*)(src + i);
        *(uint2*)(dst + i) = f4h(v);
    }
}

// ---------------------------------------------------------------------------
// FP16 tensor-core GEMM (NT): C[m][n] = sum_k A[m][k] * B[n][k]
// A, B are half row-major. CTA tile 128x256x32, 8 warps, warp tile 64x64.
// Smem: half2-packed, row stride 20 half2 (conflict-free fragment loads).
// HOUT=1 -> half output, HOUT=0 -> float output.
// ---------------------------------------------------------------------------
#define TBM 128
#define TBN 256
#define TBK 32
#define AST2 20   // half2 per row

#define GEMM_SMEM_WORDS (2 * (TBM + TBN) * AST2)   // 60 KB

template<int HOUT>
__global__ __launch_bounds__(256) void gemm_h(const __half* __restrict__ A,
                                              const __half* __restrict__ B,
                                              void* __restrict__ Cv,
                                              int M, int N, int K)
{
    extern __shared__ uint32_t smw[];
    uint32_t* As[2] = { smw, smw + TBM * AST2 };
    uint32_t* Bs[2] = { smw + 2 * TBM * AST2, smw + 2 * TBM * AST2 + TBN * AST2 };

    const int bm = blockIdx.y * TBM;
    const int bn = blockIdx.x * TBN;
    const int tid = threadIdx.x;
    const int warp = tid >> 5;
    const int lane = tid & 31;
    const int g = lane >> 2;
    const int cth = lane & 3;
    const int wm = warp & 1;
    const int wn = warp >> 1;

    // loader: 4 threads per row, 8 halves (uint4) each; 64 rows per pass
    const int ar = tid >> 2;             // 0..63
    const int ac = (tid & 3) * 8;        // half col 0,8,16,24
    const int ah = (tid & 3) * 4;        // half2 col

    float acc[4][8][4];
#pragma unroll
    for (int mi = 0; mi < 4; mi++)
#pragma unroll
        for (int ni = 0; ni < 8; ni++)
#pragma unroll
            for (int e = 0; e < 4; e++) acc[mi][ni][e] = 0.f;

    const int ntiles = K / TBK;   // 64

    uint4 ra[2], rb[4];
#pragma unroll
    for (int p = 0; p < 2; p++)
        ra[p] = *(const uint4*)(A + (size_t)(bm + ar + 64 * p) * K + ac);
#pragma unroll
    for (int p = 0; p < 4; p++)
        rb[p] = *(const uint4*)(B + (size_t)(bn + ar + 64 * p) * K + ac);
#pragma unroll
    for (int p = 0; p < 2; p++)
        *(uint4*)(As[0] + (ar + 64 * p) * AST2 + ah) = ra[p];
#pragma unroll
    for (int p = 0; p < 4; p++)
        *(uint4*)(Bs[0] + (ar + 64 * p) * AST2 + ah) = rb[p];
    __syncthreads();

    for (int t = 0; t < ntiles; t++) {
        if (t + 1 < ntiles) {
            const int off = (t + 1) * TBK + ac;
#pragma unroll
            for (int p = 0; p < 2; p++)
                ra[p] = *(const uint4*)(A + (size_t)(bm + ar + 64 * p) * K + off);
#pragma unroll
            for (int p = 0; p < 4; p++)
                rb[p] = *(const uint4*)(B + (size_t)(bn + ar + 64 * p) * K + off);
        }

        const uint32_t* as = As[t & 1];
        const uint32_t* bs = Bs[t & 1];

#pragma unroll
        for (int kch = 0; kch < 2; kch++) {
            const int kb = kch * 8;
            uint32_t a[4][4], b[8][2];
#pragma unroll
            for (int mi = 0; mi < 4; mi++) {
                const int rb0 = wm * 64 + mi * 16 + g;
                a[mi][0] = as[rb0 * AST2 + kb + cth];
                a[mi][1] = as[(rb0 + 8) * AST2 + kb + cth];
                a[mi][2] = as[rb0 * AST2 + kb + cth + 4];
                a[mi][3] = as[(rb0 + 8) * AST2 + kb + cth + 4];
            }
#pragma unroll
            for (int ni = 0; ni < 8; ni++) {
                const int cb = wn * 64 + ni * 8 + g;
                b[ni][0] = bs[cb * AST2 + kb + cth];
                b[ni][1] = bs[cb * AST2 + kb + cth + 4];
            }
#pragma unroll
            for (int mi = 0; mi < 4; mi++)
#pragma unroll
                for (int ni = 0; ni < 8; ni++)
                    mma_f16(acc[mi][ni], a[mi][0], a[mi][1], a[mi][2], a[mi][3],
                            b[ni][0], b[ni][1]);
        }

        if (t + 1 < ntiles) {
            uint32_t* asn = As[(t + 1) & 1];
            uint32_t* bsn = Bs[(t + 1) & 1];
#pragma unroll
            for (int p = 0; p < 2; p++)
                *(uint4*)(asn + (ar + 64 * p) * AST2 + ah) = ra[p];
#pragma unroll
            for (int p = 0; p < 4; p++)
                *(uint4*)(bsn + (ar + 64 * p) * AST2 + ah) = rb[p];
            __syncthreads();
        }
    }

    // Epilogue
#pragma unroll
    for (int mi = 0; mi < 4; mi++) {
        const int r0 = bm + wm * 64 + mi * 16 + g;
#pragma unroll
        for (int ni = 0; ni < 8; ni++) {
            const int col = bn + wn * 64 + ni * 8 + cth * 2;
            if (HOUT) {
                __half* C = (__half*)Cv;
                *(uint32_t*)(C + (size_t)r0 * N + col) = f2h2(acc[mi][ni][0], acc[mi][ni][1]);
                *(uint32_t*)(C + (size_t)(r0 + 8) * N + col) = f2h2(acc[mi][ni][2], acc[mi][ni][3]);
            } else {
                float* C = (float*)Cv;
                *(float2*)(C + (size_t)r0 * N + col) = make_float2(acc[mi][ni][0], acc[mi][ni][1]);
                *(float2*)(C + (size_t)(r0 + 8) * N + col) = make_float2(acc[mi][ni][2], acc[mi][ni][3]);
            }
        }
    }
}

// ---------------------------------------------------------------------------
// Fused per-head RMSNorm + RoPE. Reads fp32 (GEMM out), writes fp16.
// q path folds the 1/sqrt(HD) attention scale. grid.z selects q/k.
// ---------------------------------------------------------------------------
__global__ __launch_bounds__(128) void rmsnorm_rope_kernel(const float* __restrict__ qsrc,
                                                           const float* __restrict__ ksrc,
                                                           __half* __restrict__ qdst,
                                                           __half* __restrict__ kdst,
                                                           const float* __restrict__ qw,
                                                           const float* __restrict__ kw,
                                                           const float* __restrict__ cos_t,
                                                           const float* __restrict__ sin_t)
{
    const int token = blockIdx.y;
    const int h = blockIdx.x;
    const int d = threadIdx.x;
    const int s = token & (SS - 1);

    const float* src = blockIdx.z ? ksrc : qsrc;
    __half* dst = blockIdx.z ? kdst : qdst;
    const float* w = blockIdx.z ? kw : qw;
    const float oscale = blockIdx.z ? 1.0f : 0.08838834764831845f;

    const float* sptr = src + (size_t)token * DIM + h * HD;
    float v = sptr[d];

    float sq = v * v;
#pragma unroll
    for (int off = 16; off > 0; off >>= 1)
        sq += __shfl_xor_sync(0xffffffffu, sq, off);

    __shared__ float wsum[4];
    const int wid = d >> 5;
    if ((d & 31) == 0) wsum[wid] = sq;
    __syncthreads();
    float tot = wsum[0] + wsum[1] + wsum[2] + wsum[3];

    float rms = rsqrtf(tot * (1.0f / HD) + EPSF);
    float xn = v * rms * w[d];

    __shared__ float xs[HD];
    xs[d] = xn;
    __syncthreads();

    float rot = (d < 64) ? -xs[d + 64] : xs[d - 64];
    float out = (xn * cos_t[s * HD + d] + rot * sin_t[s * HD + d]) * oscale;
    dst[(size_t)token * DIM + h * HD + d] = __float2half_rn(out);
}

// ---------------------------------------------------------------------------
// Causal flash attention, fp16 in / fp16 out, m16n8k16.
// BQ=128, BK=64, HD=128. 8 warps; warp w owns q-rows w*16..+15.
// ---------------------------------------------------------------------------
#define FBQ 128
#define FBK 64
#define QS2 68   // half2 per Q/K row
#define VT2 36   // half2 per Vt row (keys)
#define PS2 36   // half2 per P row

#define FLASH_SMEM_WORDS (FBQ * QS2 + FBK * QS2 + HD * VT2 + FBQ * PS2)

__global__ __launch_bounds__(256) void flash_f16(const __half* __restrict__ q,
                                                 const __half* __restrict__ k,
                                                 const __half* __restrict__ v,
                                                 __half* __restrict__ o)
{
    extern __shared__ uint32_t smh[];
    uint32_t* Qs2 = smh;                       // 128 x 68
    uint32_t* Ks2 = Qs2 + FBQ * QS2;           // 64 x 68
    uint32_t* Vt2 = Ks2 + FBK * QS2;           // 128 x 36 (row = hd, col = key)
    uint32_t* Ps2 = Vt2 + HD * VT2;            // 128 x 36
    __half*  VtH = (__half*)Vt2;

    const int q0 = blockIdx.x * FBQ;
    const int bh = blockIdx.y;
    const int b = bh >> 4;
    const int h = bh & 15;
    const size_t base = (size_t)b * SS * DIM + (size_t)h * HD;

    const int tid = threadIdx.x;
    const int w = tid >> 5;
    const int lane = tid & 31;
    const int g = lane >> 2;
    const int cth = lane & 3;

    // ---- Load Q tile: pure half copy, 2048 uint4 ----
#pragma unroll
    for (int p = 0; p < 8; p++) {
        int idx = tid + p * 256;
        int r = idx >> 4;
        int c = idx & 15;
        uint4 u = *(const uint4*)(q + base + (size_t)(q0 + r) * DIM + c * 8);
        *(uint4*)(Qs2 + r * QS2 + c * 4) = u;
    }

    float m0 = -INFINITY, m1 = -INFINITY, l0 = 0.f, l1 = 0.f;
    float acc[16][4];
#pragma unroll
    for (int nb = 0; nb < 16; nb++)
#pragma unroll
        for (int e = 0; e < 4; e++) acc[nb][e] = 0.f;

    const int rowg = q0 + w * 16 + g;
    uint32_t* Qw2 = Qs2 + (w * 16) * QS2;
    uint32_t* Pw2 = Ps2 + (w * 16) * PS2;

    const int nkb = q0 / FBK + 2;
    for (int kb = 0; kb < nkb; kb++) {
        const int k0 = kb * FBK;
        __syncthreads();

        // ---- K tile: 1024 uint4 copies ----
#pragma unroll
        for (int p = 0; p < 4; p++) {
            int idx = tid + p * 256;
            int r = idx >> 4;
            int c = idx & 15;
            uint4 u = *(const uint4*)(k + base + (size_t)(k0 + r) * DIM + c * 8);
            *(uint4*)(Ks2 + r * QS2 + c * 4) = u;
        }
        // ---- V tile TRANSPOSED: Vt[hd][key] ----
#pragma unroll
        for (int p = 0; p < 4; p++) {
            int idx = tid + p * 256;
            int key = idx & 63;
            int hd8 = (idx >> 6) * 8;
            uint4 u = *(const uint4*)(v + base + (size_t)(k0 + key) * DIM + hd8);
            __half hv[8];
            *(uint4*)hv = u;
#pragma unroll
            for (int j = 0; j < 8; j++)
                VtH[(hd8 + j) * (2 * VT2) + key] = hv[j];
        }
        __syncthreads();

        if (k0 > q0 + w * 16 + 15) continue;

        // ---- S = Q K^T ----
        float c[8][4];
#pragma unroll
        for (int nb = 0; nb < 8; nb++)
#pragma unroll
            for (int e = 0; e < 4; e++) c[nb][e] = 0.f;

#pragma unroll 2
        for (int kc = 0; kc < 8; kc++) {
            const int kh = kc * 8;
            uint32_t a0 = Qw2[g * QS2 + kh + cth];
            uint32_t a1 = Qw2[(g + 8) * QS2 + kh + cth];
            uint32_t a2 = Qw2[g * QS2 + kh + cth + 4];
            uint32_t a3 = Qw2[(g + 8) * QS2 + kh + cth + 4];
#pragma unroll
            for (int nb = 0; nb < 8; nb++) {
                const int n = nb * 8 + g;
                uint32_t b0 = Ks2[n * QS2 + kh + cth];
                uint32_t b1 = Ks2[n * QS2 + kh + cth + 4];
                mma_f16(c[nb], a0, a1, a2, a3, b0, b1);
            }
        }

        // ---- causal mask ----
        if (k0 + FBK - 1 > rowg) {
#pragma unroll
            for (int nb = 0; nb < 8; nb++) {
                const int col = k0 + nb * 8 + 2 * cth;
                if (col > rowg)         c[nb][0] = -INFINITY;
                if (col + 1 > rowg)     c[nb][1] = -INFINITY;
                if (col > rowg + 8)     c[nb][2] = -INFINITY;
                if (col + 1 > rowg + 8) c[nb][3] = -INFINITY;
            }
        }

        // ---- online softmax ----
        float mx0 = -INFINITY, mx1 = -INFINITY;
#pragma unroll
        for (int nb = 0; nb < 8; nb++) {
            mx0 = fmaxf(mx0, fmaxf(c[nb][0], c[nb][1]));
            mx1 = fmaxf(mx1, fmaxf(c[nb][2], c[nb][3]));
        }
        mx0 = fmaxf(mx0, __shfl_xor_sync(0xffffffffu, mx0, 1));
        mx0 = fmaxf(mx0, __shfl_xor_sync(0xffffffffu, mx0, 2));
        mx1 = fmaxf(mx1, __shfl_xor_sync(0xffffffffu, mx1, 1));
        mx1 = fmaxf(mx1, __shfl_xor_sync(0xffffffffu, mx1, 2));

        const float mn0 = fmaxf(m0, mx0);
        const float mn1 = fmaxf(m1, mx1);
        float rs0 = 0.f, rs1 = 0.f;
#pragma unroll
        for (int nb = 0; nb < 8; nb++) {
            c[nb][0] = __expf(c[nb][0] - mn0);
            c[nb][1] = __expf(c[nb][1] - mn0);
            c[nb][2] = __expf(c[nb][2] - mn1);
            c[nb][3] = __expf(c[nb][3] - mn1);
            rs0 += c[nb][0] + c[nb][1];
            rs1 += c[nb][2] + c[nb][3];
        }
        rs0 += __shfl_xor_sync(0xffffffffu, rs0, 1);
        rs0 += __shfl_xor_sync(0xffffffffu, rs0, 2);
        rs1 += __shfl_xor_sync(0xffffffffu, rs1, 1);
        rs1 += __shfl_xor_sync(0xffffffffu, rs1, 2);

        const float al0 = __expf(m0 - mn0);
        const float al1 = __expf(m1 - mn1);
        l0 = l0 * al0 + rs0;
        l1 = l1 * al1 + rs1;
        m0 = mn0;
        m1 = mn1;

#pragma unroll
        for (int nb = 0; nb < 16; nb++) {
            acc[nb][0] *= al0; acc[nb][1] *= al0;
            acc[nb][2] *= al1; acc[nb][3] *= al1;
        }

        // ---- stage P (fp16) ----
#pragma unroll
        for (int nb = 0; nb < 8; nb++) {
            Pw2[g * PS2 + nb * 4 + cth]       = f2h2(c[nb][0], c[nb][1]);
            Pw2[(g + 8) * PS2 + nb * 4 + cth] = f2h2(c[nb][2], c[nb][3]);
        }
        __syncwarp();

        // ---- O += P V ----
#pragma unroll
        for (int kc = 0; kc < 4; kc++) {
            const int kh = kc * 8;
            uint32_t a0 = Pw2[g * PS2 + kh + cth];
            uint32_t a1 = Pw2[(g + 8) * PS2 + kh + cth];
            uint32_t a2 = Pw2[g * PS2 + kh + cth + 4];
            uint32_t a3 = Pw2[(g + 8) * PS2 + kh + cth + 4];
#pragma unroll
            for (int nb = 0; nb < 16; nb++) {
                const int n = nb * 8 + g;
                uint32_t b0 = Vt2[n * VT2 + kh + cth];
                uint32_t b1 = Vt2[n * VT2 + kh + cth + 4];
                mma_f16(acc[nb], a0, a1, a2, a3, b0, b1);
            }
        }
        __syncwarp();
    }

    // ---- epilogue: half out ----
    const float il0 = 1.0f / l0;
    const float il1 = 1.0f / l1;
    const size_t r0 = (size_t)rowg;
    const size_t r1 = (size_t)(rowg + 8);
#pragma unroll
    for (int nb = 0; nb < 16; nb++) {
        const int col = nb * 8 + 2 * cth;
        *(uint32_t*)(o + base + r0 * DIM + col) = f2h2(acc[nb][0] * il0, acc[nb][1] * il0);
        *(uint32_t*)(o + base + r1 * DIM + col) = f2h2(acc[nb][2] * il1, acc[nb][3] * il1);
    }
}

// ---------------------------------------------------------------------------
// Launch
// Inputs: 0=x 1=rope_cos 2=rope_sin 3=attn_mask 4=wq 5=wk 6=wv 7=wo
//         8=q_norm_w 9=k_norm_w
// ---------------------------------------------------------------------------
extern "C" void kernel_launch(void* const* d_in, const int* in_sizes, int n_in,
                              void* d_out, int out_size)
{
    const float* x       = (const float*)d_in[0];
    const float* rope_c  = (const float*)d_in[1];
    const float* rope_s  = (const float*)d_in[2];
    const float* wq      = (const float*)d_in[4];
    const float* wk      = (const float*)d_in[5];
    const float* wv      = (const float*)d_in[6];
    const float* wo      = (const float*)d_in[7];
    const float* qnw     = (const float*)d_in[8];
    const float* knw     = (const float*)d_in[9];
    float* out = (float*)d_out;

    float *qf, *kf;
    __half *xh, *qh, *kh, *vh, *oh, *wqh, *wkh, *wvh, *woh;
    cudaGetSymbolAddress((void**)&qf, g_qf);
    cudaGetSymbolAddress((void**)&kf, g_kf);
    cudaGetSymbolAddress((void**)&xh, g_xh);
    cudaGetSymbolAddress((void**)&qh, g_qh);
    cudaGetSymbolAddress((void**)&kh, g_kh);
    cudaGetSymbolAddress((void**)&vh, g_vh);
    cudaGetSymbolAddress((void**)&oh, g_oh);
    cudaGetSymbolAddress((void**)&wqh, g_wqh);
    cudaGetSymbolAddress((void**)&wkh, g_wkh);
    cudaGetSymbolAddress((void**)&wvh, g_wvh);
    cudaGetSymbolAddress((void**)&woh, g_woh);

    // Convert inputs to fp16 once
    const int NX = TOK * DIM, NW = DIM * DIM;
    f2h_kernel<<<NX / 4 / 256, 256>>>(x, xh, NX);
    f2h_kernel<<<NW / 4 / 256, 256>>>(wq, wqh, NW);
    f2h_kernel<<<NW / 4 / 256, 256>>>(wk, wkh, NW);
    f2h_kernel<<<NW / 4 / 256, 256>>>(wv, wvh, NW);
    f2h_kernel<<<NW / 4 / 256, 256>>>(wo, woh, NW);

    const int gemm_smem = GEMM_SMEM_WORDS * sizeof(uint32_t);  // 60 KB
    cudaFuncSetAttribute(gemm_h<0>, cudaFuncAttributeMaxDynamicSharedMemorySize, gemm_smem);
    cudaFuncSetAttribute(gemm_h<1>, cudaFuncAttributeMaxDynamicSharedMemorySize, gemm_smem);

    dim3 ggrid(DIM / TBN, TOK / TBM);  // (8, 64)
    gemm_h<0><<<ggrid, 256, gemm_smem>>>(xh, wqh, qf, TOK, DIM, DIM);
    gemm_h<0><<<ggrid, 256, gemm_smem>>>(xh, wkh, kf, TOK, DIM, DIM);
    gemm_h<1><<<ggrid, 256, gemm_smem>>>(xh, wvh, vh, TOK, DIM, DIM);

    dim3 ngrid(NH, TOK, 2);
    rmsnorm_rope_kernel<<<ngrid, 128>>>(qf, kf, qh, kh, qnw, knw, rope_c, rope_s);

    const int flash_smem = FLASH_SMEM_WORDS * sizeof(uint32_t);  // ~89 KB
    cudaFuncSetAttribute(flash_f16, cudaFuncAttributeMaxDynamicSharedMemorySize,
                         flash_smem);
    dim3 fgrid(SS / FBQ, BB * NH);  // (16, 64)
    flash_f16<<<fgrid, 256, flash_smem>>>(qh, kh, vh, oh);

    gemm_h<0><<<ggrid, 256, gemm_smem>>>(oh, woh, out, TOK, DIM, DIM);
}